// round 4
// baseline (speedup 1.0000x reference)
#include <cuda_runtime.h>
#include <cuda_bf16.h>
#include <math.h>

// ---------------------------------------------------------------------------
// Problem constants
// ---------------------------------------------------------------------------
#define TOK      8192       // B*T tokens (4*2*1024)
#define IDIM     256
#define NU       512        // N_UNITS
#define EU       2048       // E_UNITS
#define NLAYERS  4
#define HEADS    8
#define DK       64
#define SEQ      1024
#define NBATCH   8          // bs*num

// ---------------------------------------------------------------------------
// Scratch (static device memory; allocation APIs are forbidden)
// ---------------------------------------------------------------------------
__device__ float g_e  [TOK * NU];
__device__ float g_q  [TOK * NU];
__device__ float g_k  [TOK * NU];
__device__ float g_v  [TOK * NU];
__device__ float g_ctx[TOK * NU];
__device__ float g_h  [TOK * EU];

// ---------------------------------------------------------------------------
// GEMM: C[M,N] = A[M,K] @ W[N,K]^T + bias (+ optional ReLU, + optional residual)
// 128x128 block tile, 16 K-slab, 8x8 register micro-tile, 256 threads.
// M,N,K are all multiples of the tile sizes for every call in this problem.
// ---------------------------------------------------------------------------
template<bool RELU, bool RES>
__global__ __launch_bounds__(256) void gemm_kernel(
    const float* __restrict__ A, const float* __restrict__ W,
    const float* __restrict__ bias, const float* __restrict__ res,
    float* __restrict__ C, int M, int N, int K)
{
    __shared__ float As[16][128];
    __shared__ float Ws[16][128];

    const int tid = threadIdx.x;
    const int tx  = tid & 15;        // 0..15 -> N direction
    const int ty  = tid >> 4;        // 0..15 -> M direction
    const int n0  = blockIdx.x * 128;
    const int m0  = blockIdx.y * 128;

    const float* Ap = A + (size_t)m0 * K;
    const float* Wp = W + (size_t)n0 * K;

    float acc[8][8];
#pragma unroll
    for (int i = 0; i < 8; i++)
#pragma unroll
        for (int j = 0; j < 8; j++) acc[i][j] = 0.0f;

    for (int k0 = 0; k0 < K; k0 += 16) {
        // cooperative load: 128x16 tiles of A and W, stored K-transposed
#pragma unroll
        for (int i = 0; i < 2; i++) {
            int idx = tid + i * 256;          // 0..511
            int r   = idx >> 2;               // 0..127
            int c4  = (idx & 3) * 4;          // 0,4,8,12
            float4 va = *(const float4*)(Ap + (size_t)r * K + k0 + c4);
            As[c4 + 0][r] = va.x; As[c4 + 1][r] = va.y;
            As[c4 + 2][r] = va.z; As[c4 + 3][r] = va.w;
            float4 vw = *(const float4*)(Wp + (size_t)r * K + k0 + c4);
            Ws[c4 + 0][r] = vw.x; Ws[c4 + 1][r] = vw.y;
            Ws[c4 + 2][r] = vw.z; Ws[c4 + 3][r] = vw.w;
        }
        __syncthreads();

#pragma unroll
        for (int kk = 0; kk < 16; kk++) {
            float a[8], b[8];
            *(float4*)&a[0] = *(const float4*)&As[kk][ty * 8];
            *(float4*)&a[4] = *(const float4*)&As[kk][ty * 8 + 4];
            *(float4*)&b[0] = *(const float4*)&Ws[kk][tx * 8];
            *(float4*)&b[4] = *(const float4*)&Ws[kk][tx * 8 + 4];
#pragma unroll
            for (int i = 0; i < 8; i++)
#pragma unroll
                for (int j = 0; j < 8; j++)
                    acc[i][j] += a[i] * b[j];
        }
        __syncthreads();
    }

    // epilogue
#pragma unroll
    for (int i = 0; i < 8; i++) {
        int m = m0 + ty * 8 + i;
#pragma unroll
        for (int j = 0; j < 8; j += 4) {
            int n = n0 + tx * 8 + j;
            float4 bv = *(const float4*)(bias + n);
            float4 o;
            o.x = acc[i][j + 0] + bv.x;
            o.y = acc[i][j + 1] + bv.y;
            o.z = acc[i][j + 2] + bv.z;
            o.w = acc[i][j + 3] + bv.w;
            if (RELU) {
                o.x = fmaxf(o.x, 0.0f); o.y = fmaxf(o.y, 0.0f);
                o.z = fmaxf(o.z, 0.0f); o.w = fmaxf(o.w, 0.0f);
            }
            if (RES) {
                float4 rv = *(const float4*)(res + (size_t)m * N + n);
                o.x += rv.x; o.y += rv.y; o.z += rv.z; o.w += rv.w;
            }
            *(float4*)(C + (size_t)m * N + n) = o;
        }
    }
}

// ---------------------------------------------------------------------------
// LayerNorm over rows of 512 (works in-place). 128 threads, float4 per thread.
// ---------------------------------------------------------------------------
__global__ __launch_bounds__(128) void ln_kernel(
    const float* __restrict__ X, const float* __restrict__ gamma,
    const float* __restrict__ beta, float* __restrict__ O)
{
    __shared__ float red[4];
    const int row = blockIdx.x;
    const int tid = threadIdx.x;

    float4 v = *(const float4*)(X + (size_t)row * NU + tid * 4);
    float s = v.x + v.y + v.z + v.w;
#pragma unroll
    for (int o = 16; o > 0; o >>= 1) s += __shfl_xor_sync(0xffffffffu, s, o);
    if ((tid & 31) == 0) red[tid >> 5] = s;
    __syncthreads();
    float mean = (red[0] + red[1] + red[2] + red[3]) * (1.0f / 512.0f);
    __syncthreads();

    float dx = v.x - mean, dy = v.y - mean, dz = v.z - mean, dw = v.w - mean;
    float sq = dx * dx + dy * dy + dz * dz + dw * dw;
#pragma unroll
    for (int o = 16; o > 0; o >>= 1) sq += __shfl_xor_sync(0xffffffffu, sq, o);
    if ((tid & 31) == 0) red[tid >> 5] = sq;
    __syncthreads();
    float var = (red[0] + red[1] + red[2] + red[3]) * (1.0f / 512.0f);
    float inv = rsqrtf(var + 1e-5f);

    float4 g = *(const float4*)(gamma + tid * 4);
    float4 b = *(const float4*)(beta  + tid * 4);
    float4 o4;
    o4.x = dx * inv * g.x + b.x;
    o4.y = dy * inv * g.y + b.y;
    o4.z = dz * inv * g.z + b.z;
    o4.w = dw * inv * g.w + b.w;
    *(float4*)(O + (size_t)row * NU + tid * 4) = o4;
}

// ---------------------------------------------------------------------------
// Attention: one block handles 8 query rows of one (b,h).
// Full 1024-wide score rows held in smem; K/V streamed in 32-row tiles.
// ---------------------------------------------------------------------------
__global__ __launch_bounds__(128) void attn_kernel(
    const float* __restrict__ Q, const float* __restrict__ K,
    const float* __restrict__ V, float* __restrict__ O)
{
    __shared__ float Ss[8][1024];     // scores / probs
    __shared__ float KVs[32][68];     // K or V tile (padded rows)
    __shared__ float rowsum[8];

    const int tid = threadIdx.x;
    const int qt = blockIdx.x;        // 0..127 (query tile of 8)
    const int h  = blockIdx.y;        // 0..7
    const int b  = blockIdx.z;        // 0..7
    const int qr = tid >> 4;          // 0..7  thread's query row
    const int sl = tid & 15;

    const size_t base = ((size_t)b * SEQ) * NU + (size_t)h * DK;

    // this thread's query row in registers (16 x float4 = 64 floats)
    float4 qreg[16];
    {
        const float* qp = Q + base + (size_t)(qt * 8 + qr) * NU;
#pragma unroll
        for (int i = 0; i < 16; i++) qreg[i] = *(const float4*)(qp + i * 4);
    }

    // ---- phase 1: scores = Q K^T * scale ----
    for (int st = 0; st < 32; st++) {
        int s0 = st * 32;
#pragma unroll
        for (int i = 0; i < 4; i++) {
            int idx = tid + i * 128;          // 0..511
            int r   = idx >> 4;               // 0..31
            int c4  = (idx & 15) * 4;         // 0..60
            *(float4*)&KVs[r][c4] =
                *(const float4*)(K + base + (size_t)(s0 + r) * NU + c4);
        }
        __syncthreads();
#pragma unroll
        for (int ss = 0; ss < 2; ss++) {
            int s = sl + ss * 16;
            float a = 0.0f;
#pragma unroll
            for (int i = 0; i < 16; i++) {
                float4 kk = *(const float4*)&KVs[s][i * 4];
                a += qreg[i].x * kk.x + qreg[i].y * kk.y
                   + qreg[i].z * kk.z + qreg[i].w * kk.w;
            }
            Ss[qr][s0 + s] = a * 0.125f;     // 1/sqrt(64)
        }
        __syncthreads();
    }

    // ---- phase 2: softmax (unnormalized; keep row sums) ----
    {
        const int warp = tid >> 5, lane = tid & 31;
        for (int r = warp; r < 8; r += 4) {
            float m = -1e30f;
            for (int j = lane; j < 1024; j += 32) m = fmaxf(m, Ss[r][j]);
#pragma unroll
            for (int o = 16; o > 0; o >>= 1)
                m = fmaxf(m, __shfl_xor_sync(0xffffffffu, m, o));
            float sum = 0.0f;
            for (int j = lane; j < 1024; j += 32) {
                float p = __expf(Ss[r][j] - m);
                Ss[r][j] = p;
                sum += p;
            }
#pragma unroll
            for (int o = 16; o > 0; o >>= 1)
                sum += __shfl_xor_sync(0xffffffffu, sum, o);
            if (lane == 0) rowsum[r] = sum;
        }
    }
    __syncthreads();

    // ---- phase 3: ctx = P V ----
    const int d0 = (tid & 15) * 4;
    float4 acc = make_float4(0.f, 0.f, 0.f, 0.f);
    for (int st = 0; st < 32; st++) {
        int s0 = st * 32;
#pragma unroll
        for (int i = 0; i < 4; i++) {
            int idx = tid + i * 128;
            int r   = idx >> 4;
            int c4  = (idx & 15) * 4;
            *(float4*)&KVs[r][c4] =
                *(const float4*)(V + base + (size_t)(s0 + r) * NU + c4);
        }
        __syncthreads();
#pragma unroll
        for (int s = 0; s < 32; s++) {
            float p = Ss[qr][s0 + s];
            float4 vv = *(const float4*)&KVs[s][d0];
            acc.x += p * vv.x; acc.y += p * vv.y;
            acc.z += p * vv.z; acc.w += p * vv.w;
        }
        __syncthreads();
    }

    float inv = 1.0f / rowsum[qr];
    float4 o4 = make_float4(acc.x * inv, acc.y * inv, acc.z * inv, acc.w * inv);
    *(float4*)(O + base + (size_t)(qt * 8 + qr) * NU + d0) = o4;
}

// ---------------------------------------------------------------------------
// Host orchestration (graph-capturable: kernel launches only)
// ---------------------------------------------------------------------------
extern "C" void kernel_launch(void* const* d_in, const int* in_sizes, int n_in,
                              void* d_out, int out_size)
{
    (void)in_sizes; (void)n_in; (void)out_size;

    const float* x     = (const float*)d_in[0];
    const float* Win   = (const float*)d_in[1];
    const float* bin   = (const float*)d_in[2];
    const float* ln1_g = (const float*)d_in[3];
    const float* ln1_b = (const float*)d_in[4];
    const float* Wq    = (const float*)d_in[5];
    const float* bq    = (const float*)d_in[6];
    const float* Wk    = (const float*)d_in[7];
    const float* bk    = (const float*)d_in[8];
    const float* Wv    = (const float*)d_in[9];
    const float* bv    = (const float*)d_in[10];
    const float* Wo    = (const float*)d_in[11];
    const float* bo    = (const float*)d_in[12];
    const float* ln2_g = (const float*)d_in[13];
    const float* ln2_b = (const float*)d_in[14];
    const float* W1    = (const float*)d_in[15];
    const float* b1    = (const float*)d_in[16];
    const float* W2    = (const float*)d_in[17];
    const float* b2    = (const float*)d_in[18];
    const float* lno_g = (const float*)d_in[19];
    const float* lno_b = (const float*)d_in[20];
    float* out = (float*)d_out;

    float *e, *q, *k, *v, *ctx, *hbuf;
    cudaGetSymbolAddress((void**)&e,    g_e);
    cudaGetSymbolAddress((void**)&q,    g_q);
    cudaGetSymbolAddress((void**)&k,    g_k);
    cudaGetSymbolAddress((void**)&v,    g_v);
    cudaGetSymbolAddress((void**)&ctx,  g_ctx);
    cudaGetSymbolAddress((void**)&hbuf, g_h);

    const int M = TOK;
    dim3 g512(NU / 128, M / 128);     // (4, 64)
    dim3 g2048(EU / 128, M / 128);    // (16, 64)
    dim3 gattn(SEQ / 8, HEADS, NBATCH);

    // input projection: e = x @ Win^T + bin
    gemm_kernel<false, false><<<g512, 256>>>(x, Win, bin, nullptr, e, M, NU, IDIM);

    for (int i = 0; i < NLAYERS; i++) {
        const size_t wo = (size_t)i * NU * NU;
        const size_t w1o = (size_t)i * EU * NU;

        ln_kernel<<<M, 128>>>(e, ln1_g + i * NU, ln1_b + i * NU, e);

        gemm_kernel<false, false><<<g512, 256>>>(e, Wq + wo, bq + i * NU, nullptr, q, M, NU, NU);
        gemm_kernel<false, false><<<g512, 256>>>(e, Wk + wo, bk + i * NU, nullptr, k, M, NU, NU);
        gemm_kernel<false, false><<<g512, 256>>>(e, Wv + wo, bv + i * NU, nullptr, v, M, NU, NU);

        attn_kernel<<<gattn, 128>>>(q, k, v, ctx);

        // e = e + ctx @ Wo^T + bo
        gemm_kernel<false, true><<<g512, 256>>>(ctx, Wo + wo, bo + i * NU, e, e, M, NU, NU);

        ln_kernel<<<M, 128>>>(e, ln2_g + i * NU, ln2_b + i * NU, e);

        // hdn = relu(e @ W1^T + b1)
        gemm_kernel<true, false><<<g2048, 256>>>(e, W1 + w1o, b1 + (size_t)i * EU, nullptr, hbuf, M, EU, NU);
        // e = e + hdn @ W2^T + b2
        gemm_kernel<false, true><<<g512, 256>>>(hbuf, W2 + w1o, b2 + i * NU, e, e, M, NU, EU);
    }

    ln_kernel<<<M, 128>>>(e, lno_g, lno_b, out);
}

// round 5
// speedup vs baseline: 1.0001x; 1.0001x over previous
#include <cuda_runtime.h>
#include <cuda_bf16.h>
#include <math.h>

// ---------------------------------------------------------------------------
// Problem constants
// ---------------------------------------------------------------------------
#define TOK      8192       // B*T tokens (4*2*1024)
#define IDIM     256
#define NU       512        // N_UNITS
#define EU       2048       // E_UNITS
#define NLAYERS  4
#define HEADS    8
#define DK       64
#define SEQ      1024
#define NBATCH   8          // bs*num

// ---------------------------------------------------------------------------
// Scratch (static device memory; allocation APIs are forbidden)
// ---------------------------------------------------------------------------
__device__ float g_e  [TOK * NU];
__device__ float g_q  [TOK * NU];
__device__ float g_k  [TOK * NU];
__device__ float g_v  [TOK * NU];
__device__ float g_ctx[TOK * NU];
__device__ float g_h  [TOK * EU];

// ---------------------------------------------------------------------------
// GEMM: C[M,N] = A[M,K] @ W[N,K]^T + bias (+ optional ReLU, + optional residual)
// 128x128 block tile, 16 K-slab, 8x8 register micro-tile, 256 threads.
// M,N,K are all multiples of the tile sizes for every call in this problem.
// ---------------------------------------------------------------------------
template<bool RELU, bool RES>
__global__ __launch_bounds__(256) void gemm_kernel(
    const float* __restrict__ A, const float* __restrict__ W,
    const float* __restrict__ bias, const float* __restrict__ res,
    float* __restrict__ C, int M, int N, int K)
{
    __shared__ float As[16][128];
    __shared__ float Ws[16][128];

    const int tid = threadIdx.x;
    const int tx  = tid & 15;        // 0..15 -> N direction
    const int ty  = tid >> 4;        // 0..15 -> M direction
    const int n0  = blockIdx.x * 128;
    const int m0  = blockIdx.y * 128;

    const float* Ap = A + (size_t)m0 * K;
    const float* Wp = W + (size_t)n0 * K;

    float acc[8][8];
#pragma unroll
    for (int i = 0; i < 8; i++)
#pragma unroll
        for (int j = 0; j < 8; j++) acc[i][j] = 0.0f;

    for (int k0 = 0; k0 < K; k0 += 16) {
        // cooperative load: 128x16 tiles of A and W, stored K-transposed
#pragma unroll
        for (int i = 0; i < 2; i++) {
            int idx = tid + i * 256;          // 0..511
            int r   = idx >> 2;               // 0..127
            int c4  = (idx & 3) * 4;          // 0,4,8,12
            float4 va = *(const float4*)(Ap + (size_t)r * K + k0 + c4);
            As[c4 + 0][r] = va.x; As[c4 + 1][r] = va.y;
            As[c4 + 2][r] = va.z; As[c4 + 3][r] = va.w;
            float4 vw = *(const float4*)(Wp + (size_t)r * K + k0 + c4);
            Ws[c4 + 0][r] = vw.x; Ws[c4 + 1][r] = vw.y;
            Ws[c4 + 2][r] = vw.z; Ws[c4 + 3][r] = vw.w;
        }
        __syncthreads();

#pragma unroll
        for (int kk = 0; kk < 16; kk++) {
            float a[8], b[8];
            *(float4*)&a[0] = *(const float4*)&As[kk][ty * 8];
            *(float4*)&a[4] = *(const float4*)&As[kk][ty * 8 + 4];
            *(float4*)&b[0] = *(const float4*)&Ws[kk][tx * 8];
            *(float4*)&b[4] = *(const float4*)&Ws[kk][tx * 8 + 4];
#pragma unroll
            for (int i = 0; i < 8; i++)
#pragma unroll
                for (int j = 0; j < 8; j++)
                    acc[i][j] += a[i] * b[j];
        }
        __syncthreads();
    }

    // epilogue
#pragma unroll
    for (int i = 0; i < 8; i++) {
        int m = m0 + ty * 8 + i;
#pragma unroll
        for (int j = 0; j < 8; j += 4) {
            int n = n0 + tx * 8 + j;
            float4 bv = *(const float4*)(bias + n);
            float4 o;
            o.x = acc[i][j + 0] + bv.x;
            o.y = acc[i][j + 1] + bv.y;
            o.z = acc[i][j + 2] + bv.z;
            o.w = acc[i][j + 3] + bv.w;
            if (RELU) {
                o.x = fmaxf(o.x, 0.0f); o.y = fmaxf(o.y, 0.0f);
                o.z = fmaxf(o.z, 0.0f); o.w = fmaxf(o.w, 0.0f);
            }
            if (RES) {
                float4 rv = *(const float4*)(res + (size_t)m * N + n);
                o.x += rv.x; o.y += rv.y; o.z += rv.z; o.w += rv.w;
            }
            *(float4*)(C + (size_t)m * N + n) = o;
        }
    }
}

// ---------------------------------------------------------------------------
// LayerNorm over rows of 512 (works in-place). 128 threads, float4 per thread.
// ---------------------------------------------------------------------------
__global__ __launch_bounds__(128) void ln_kernel(
    const float* __restrict__ X, const float* __restrict__ gamma,
    const float* __restrict__ beta, float* __restrict__ O)
{
    __shared__ float red[4];
    const int row = blockIdx.x;
    const int tid = threadIdx.x;

    float4 v = *(const float4*)(X + (size_t)row * NU + tid * 4);
    float s = v.x + v.y + v.z + v.w;
#pragma unroll
    for (int o = 16; o > 0; o >>= 1) s += __shfl_xor_sync(0xffffffffu, s, o);
    if ((tid & 31) == 0) red[tid >> 5] = s;
    __syncthreads();
    float mean = (red[0] + red[1] + red[2] + red[3]) * (1.0f / 512.0f);
    __syncthreads();

    float dx = v.x - mean, dy = v.y - mean, dz = v.z - mean, dw = v.w - mean;
    float sq = dx * dx + dy * dy + dz * dz + dw * dw;
#pragma unroll
    for (int o = 16; o > 0; o >>= 1) sq += __shfl_xor_sync(0xffffffffu, sq, o);
    if ((tid & 31) == 0) red[tid >> 5] = sq;
    __syncthreads();
    float var = (red[0] + red[1] + red[2] + red[3]) * (1.0f / 512.0f);
    float inv = rsqrtf(var + 1e-5f);

    float4 g = *(const float4*)(gamma + tid * 4);
    float4 b = *(const float4*)(beta  + tid * 4);
    float4 o4;
    o4.x = dx * inv * g.x + b.x;
    o4.y = dy * inv * g.y + b.y;
    o4.z = dz * inv * g.z + b.z;
    o4.w = dw * inv * g.w + b.w;
    *(float4*)(O + (size_t)row * NU + tid * 4) = o4;
}

// ---------------------------------------------------------------------------
// Attention: one block handles 8 query rows of one (b,h).
// Full 1024-wide score rows held in smem; K/V streamed in 32-row tiles.
// ---------------------------------------------------------------------------
__global__ __launch_bounds__(128) void attn_kernel(
    const float* __restrict__ Q, const float* __restrict__ K,
    const float* __restrict__ V, float* __restrict__ O)
{
    __shared__ float Ss[8][1024];     // scores / probs
    __shared__ float KVs[32][68];     // K or V tile (padded rows)
    __shared__ float rowsum[8];

    const int tid = threadIdx.x;
    const int qt = blockIdx.x;        // 0..127 (query tile of 8)
    const int h  = blockIdx.y;        // 0..7
    const int b  = blockIdx.z;        // 0..7
    const int qr = tid >> 4;          // 0..7  thread's query row
    const int sl = tid & 15;

    const size_t base = ((size_t)b * SEQ) * NU + (size_t)h * DK;

    // this thread's query row in registers (16 x float4 = 64 floats)
    float4 qreg[16];
    {
        const float* qp = Q + base + (size_t)(qt * 8 + qr) * NU;
#pragma unroll
        for (int i = 0; i < 16; i++) qreg[i] = *(const float4*)(qp + i * 4);
    }

    // ---- phase 1: scores = Q K^T * scale ----
    for (int st = 0; st < 32; st++) {
        int s0 = st * 32;
#pragma unroll
        for (int i = 0; i < 4; i++) {
            int idx = tid + i * 128;          // 0..511
            int r   = idx >> 4;               // 0..31
            int c4  = (idx & 15) * 4;         // 0..60
            *(float4*)&KVs[r][c4] =
                *(const float4*)(K + base + (size_t)(s0 + r) * NU + c4);
        }
        __syncthreads();
#pragma unroll
        for (int ss = 0; ss < 2; ss++) {
            int s = sl + ss * 16;
            float a = 0.0f;
#pragma unroll
            for (int i = 0; i < 16; i++) {
                float4 kk = *(const float4*)&KVs[s][i * 4];
                a += qreg[i].x * kk.x + qreg[i].y * kk.y
                   + qreg[i].z * kk.z + qreg[i].w * kk.w;
            }
            Ss[qr][s0 + s] = a * 0.125f;     // 1/sqrt(64)
        }
        __syncthreads();
    }

    // ---- phase 2: softmax (unnormalized; keep row sums) ----
    {
        const int warp = tid >> 5, lane = tid & 31;
        for (int r = warp; r < 8; r += 4) {
            float m = -1e30f;
            for (int j = lane; j < 1024; j += 32) m = fmaxf(m, Ss[r][j]);
#pragma unroll
            for (int o = 16; o > 0; o >>= 1)
                m = fmaxf(m, __shfl_xor_sync(0xffffffffu, m, o));
            float sum = 0.0f;
            for (int j = lane; j < 1024; j += 32) {
                float p = __expf(Ss[r][j] - m);
                Ss[r][j] = p;
                sum += p;
            }
#pragma unroll
            for (int o = 16; o > 0; o >>= 1)
                sum += __shfl_xor_sync(0xffffffffu, sum, o);
            if (lane == 0) rowsum[r] = sum;
        }
    }
    __syncthreads();

    // ---- phase 3: ctx = P V ----
    const int d0 = (tid & 15) * 4;
    float4 acc = make_float4(0.f, 0.f, 0.f, 0.f);
    for (int st = 0; st < 32; st++) {
        int s0 = st * 32;
#pragma unroll
        for (int i = 0; i < 4; i++) {
            int idx = tid + i * 128;
            int r   = idx >> 4;
            int c4  = (idx & 15) * 4;
            *(float4*)&KVs[r][c4] =
                *(const float4*)(V + base + (size_t)(s0 + r) * NU + c4);
        }
        __syncthreads();
#pragma unroll
        for (int s = 0; s < 32; s++) {
            float p = Ss[qr][s0 + s];
            float4 vv = *(const float4*)&KVs[s][d0];
            acc.x += p * vv.x; acc.y += p * vv.y;
            acc.z += p * vv.z; acc.w += p * vv.w;
        }
        __syncthreads();
    }

    float inv = 1.0f / rowsum[qr];
    float4 o4 = make_float4(acc.x * inv, acc.y * inv, acc.z * inv, acc.w * inv);
    *(float4*)(O + base + (size_t)(qt * 8 + qr) * NU + d0) = o4;
}

// ---------------------------------------------------------------------------
// Host orchestration (graph-capturable: kernel launches only)
// ---------------------------------------------------------------------------
extern "C" void kernel_launch(void* const* d_in, const int* in_sizes, int n_in,
                              void* d_out, int out_size)
{
    (void)in_sizes; (void)n_in; (void)out_size;

    const float* x     = (const float*)d_in[0];
    const float* Win   = (const float*)d_in[1];
    const float* bin   = (const float*)d_in[2];
    const float* ln1_g = (const float*)d_in[3];
    const float* ln1_b = (const float*)d_in[4];
    const float* Wq    = (const float*)d_in[5];
    const float* bq    = (const float*)d_in[6];
    const float* Wk    = (const float*)d_in[7];
    const float* bk    = (const float*)d_in[8];
    const float* Wv    = (const float*)d_in[9];
    const float* bv    = (const float*)d_in[10];
    const float* Wo    = (const float*)d_in[11];
    const float* bo    = (const float*)d_in[12];
    const float* ln2_g = (const float*)d_in[13];
    const float* ln2_b = (const float*)d_in[14];
    const float* W1    = (const float*)d_in[15];
    const float* b1    = (const float*)d_in[16];
    const float* W2    = (const float*)d_in[17];
    const float* b2    = (const float*)d_in[18];
    const float* lno_g = (const float*)d_in[19];
    const float* lno_b = (const float*)d_in[20];
    float* out = (float*)d_out;

    float *e, *q, *k, *v, *ctx, *hbuf;
    cudaGetSymbolAddress((void**)&e,    g_e);
    cudaGetSymbolAddress((void**)&q,    g_q);
    cudaGetSymbolAddress((void**)&k,    g_k);
    cudaGetSymbolAddress((void**)&v,    g_v);
    cudaGetSymbolAddress((void**)&ctx,  g_ctx);
    cudaGetSymbolAddress((void**)&hbuf, g_h);

    const int M = TOK;
    dim3 g512(NU / 128, M / 128);     // (4, 64)
    dim3 g2048(EU / 128, M / 128);    // (16, 64)
    dim3 gattn(SEQ / 8, HEADS, NBATCH);

    // input projection: e = x @ Win^T + bin
    gemm_kernel<false, false><<<g512, 256>>>(x, Win, bin, nullptr, e, M, NU, IDIM);

    for (int i = 0; i < NLAYERS; i++) {
        const size_t wo = (size_t)i * NU * NU;
        const size_t w1o = (size_t)i * EU * NU;

        ln_kernel<<<M, 128>>>(e, ln1_g + i * NU, ln1_b + i * NU, e);

        gemm_kernel<false, false><<<g512, 256>>>(e, Wq + wo, bq + i * NU, nullptr, q, M, NU, NU);
        gemm_kernel<false, false><<<g512, 256>>>(e, Wk + wo, bk + i * NU, nullptr, k, M, NU, NU);
        gemm_kernel<false, false><<<g512, 256>>>(e, Wv + wo, bv + i * NU, nullptr, v, M, NU, NU);

        attn_kernel<<<gattn, 128>>>(q, k, v, ctx);

        // e = e + ctx @ Wo^T + bo
        gemm_kernel<false, true><<<g512, 256>>>(ctx, Wo + wo, bo + i * NU, e, e, M, NU, NU);

        ln_kernel<<<M, 128>>>(e, ln2_g + i * NU, ln2_b + i * NU, e);

        // hdn = relu(e @ W1^T + b1)
        gemm_kernel<true, false><<<g2048, 256>>>(e, W1 + w1o, b1 + (size_t)i * EU, nullptr, hbuf, M, EU, NU);
        // e = e + hdn @ W2^T + b2
        gemm_kernel<false, true><<<g512, 256>>>(hbuf, W2 + w1o, b2 + i * NU, e, e, M, NU, EU);
    }

    ln_kernel<<<M, 128>>>(e, lno_g, lno_b, out);
}

// round 7
// speedup vs baseline: 1.1149x; 1.1147x over previous
#include <cuda_runtime.h>
#include <cuda_bf16.h>
#include <math.h>
#include <stdint.h>

// ---------------------------------------------------------------------------
// Problem constants
// ---------------------------------------------------------------------------
#define TOK      8192
#define IDIM     256
#define NU       512
#define EU       2048
#define NLAYERS  4
#define HEADS    8
#define DK       64
#define SEQ      1024
#define NBATCH   8

// ---------------------------------------------------------------------------
// Scratch (static device memory; allocation APIs are forbidden)
// ---------------------------------------------------------------------------
__device__ float g_e[TOK * NU];
__device__ float g_q[TOK * NU];
__device__ float g_k[TOK * NU];
__device__ float g_v[TOK * NU];

// split-bf16 operand buffers (K-concatenated: activations [hi|hi|lo], weights [hi|lo|hi])
__device__ __nv_bfloat16 g_xcvt [TOK * 3 * IDIM];
__device__ __nv_bfloat16 g_ecvt [TOK * 3 * NU];
__device__ __nv_bfloat16 g_ccvt [TOK * 3 * NU];
__device__ __nv_bfloat16 g_hcvt [TOK * 3 * EU];

__device__ __nv_bfloat16 g_Winc[NU * 3 * IDIM];
__device__ __nv_bfloat16 g_Wqc [NLAYERS * NU * 3 * NU];
__device__ __nv_bfloat16 g_Wkc [NLAYERS * NU * 3 * NU];
__device__ __nv_bfloat16 g_Wvc [NLAYERS * NU * 3 * NU];
__device__ __nv_bfloat16 g_Woc [NLAYERS * NU * 3 * NU];
__device__ __nv_bfloat16 g_W1c [NLAYERS * EU * 3 * NU];
__device__ __nv_bfloat16 g_W2c [NLAYERS * NU * 3 * EU];

// ---------------------------------------------------------------------------
// split helpers
// ---------------------------------------------------------------------------
__device__ __forceinline__ void split_bf16(float f, __nv_bfloat16& hi, __nv_bfloat16& lo) {
    hi = __float2bfloat16(f);
    lo = __float2bfloat16(f - __bfloat162float(hi));
}

// weights: out row = [hi | lo | hi], row width 3K
__global__ void convert_B_kernel(const float* __restrict__ W, __nv_bfloat16* __restrict__ out,
                                 int K, int total) {
    int idx = blockIdx.x * 256 + threadIdx.x;
    if (idx >= total) return;
    int n = idx / K, k = idx - n * K;
    __nv_bfloat16 hi, lo;
    split_bf16(W[idx], hi, lo);
    size_t base = (size_t)n * 3 * K;
    out[base + k] = hi;
    out[base + K + k] = lo;
    out[base + 2 * K + k] = hi;
}

// activations: out row = [hi | hi | lo]
__global__ void convert_A_kernel(const float* __restrict__ A, __nv_bfloat16* __restrict__ out,
                                 int K, int total) {
    int idx = blockIdx.x * 256 + threadIdx.x;
    if (idx >= total) return;
    int n = idx / K, k = idx - n * K;
    __nv_bfloat16 hi, lo;
    split_bf16(A[idx], hi, lo);
    size_t base = (size_t)n * 3 * K;
    out[base + k] = hi;
    out[base + K + k] = hi;
    out[base + 2 * K + k] = lo;
}

// ---------------------------------------------------------------------------
// mma.sync bf16 GEMM: C[M,N] = A[M,Kp] @ B[N,Kp]^T (+bias, +opt res / relu-cvt)
// 128x128 CTA tile, 256 threads (8 warps, 4x2), warp tile 32x64, K-chunk 64.
// EP: 0 = fp32 out, 1 = fp32 out + residual, 2 = relu + split-bf16 out (A-style)
// ---------------------------------------------------------------------------
#define SMPAD 72   // padded row length (bf16) -> conflict-free fragment LDS

__device__ __forceinline__ void mma16816(float* d, const uint32_t* a, const uint32_t* b) {
    asm volatile(
        "mma.sync.aligned.m16n8k16.row.col.f32.bf16.bf16.f32 "
        "{%0,%1,%2,%3}, {%4,%5,%6,%7}, {%8,%9}, {%0,%1,%2,%3};"
        : "+f"(d[0]), "+f"(d[1]), "+f"(d[2]), "+f"(d[3])
        : "r"(a[0]), "r"(a[1]), "r"(a[2]), "r"(a[3]), "r"(b[0]), "r"(b[1]));
}

template<int EP>
__global__ __launch_bounds__(256) void mma_gemm(
    const __nv_bfloat16* __restrict__ A, const __nv_bfloat16* __restrict__ B,
    const float* __restrict__ bias, const float* __restrict__ res,
    float* __restrict__ Cf, __nv_bfloat16* __restrict__ Cb,
    int N, int Kp)
{
    __shared__ __nv_bfloat16 As[128 * SMPAD];
    __shared__ __nv_bfloat16 Bs[128 * SMPAD];

    const int tid  = threadIdx.x;
    const int wid  = tid >> 5;
    const int lane = tid & 31;
    const int g    = lane >> 2;      // group id 0..7
    const int cq   = lane & 3;       // thread-in-group 0..3
    const int wm   = wid & 3;        // warp m index (0..3) -> 32 rows each
    const int wn   = wid >> 2;       // warp n index (0..1) -> 64 cols each
    const int n0   = blockIdx.x * 128;
    const int m0   = blockIdx.y * 128;

    const __nv_bfloat16* Ap = A + (size_t)m0 * Kp;
    const __nv_bfloat16* Bp = B + (size_t)n0 * Kp;

    float acc[2][8][4];
#pragma unroll
    for (int mi = 0; mi < 2; mi++)
#pragma unroll
        for (int ni = 0; ni < 8; ni++)
#pragma unroll
            for (int r = 0; r < 4; r++) acc[mi][ni][r] = 0.0f;

    const int nchunk = Kp >> 6;
    for (int c = 0; c < nchunk; c++) {
        const int k0 = c << 6;
        // load 128x64 bf16 tiles of A and B
#pragma unroll
        for (int i = 0; i < 4; i++) {
            int lin = tid + i * 256;          // 0..1023
            int r   = lin >> 3;               // 0..127
            int c8  = (lin & 7) * 8;          // bf16 col 0..56
            *(uint4*)&As[r * SMPAD + c8] = *(const uint4*)(Ap + (size_t)r * Kp + k0 + c8);
            *(uint4*)&Bs[r * SMPAD + c8] = *(const uint4*)(Bp + (size_t)r * Kp + k0 + c8);
        }
        __syncthreads();

#pragma unroll
        for (int ks = 0; ks < 4; ks++) {
            const int kb = ks * 16;
            uint32_t afr[2][4], bfr[8][2];
#pragma unroll
            for (int mi = 0; mi < 2; mi++) {
                const int rb = wm * 32 + mi * 16;
                afr[mi][0] = *(const uint32_t*)&As[(rb + g)     * SMPAD + kb + 2 * cq];
                afr[mi][1] = *(const uint32_t*)&As[(rb + g + 8) * SMPAD + kb + 2 * cq];
                afr[mi][2] = *(const uint32_t*)&As[(rb + g)     * SMPAD + kb + 8 + 2 * cq];
                afr[mi][3] = *(const uint32_t*)&As[(rb + g + 8) * SMPAD + kb + 8 + 2 * cq];
            }
#pragma unroll
            for (int ni = 0; ni < 8; ni++) {
                const int nb = wn * 64 + ni * 8;
                bfr[ni][0] = *(const uint32_t*)&Bs[(nb + g) * SMPAD + kb + 2 * cq];
                bfr[ni][1] = *(const uint32_t*)&Bs[(nb + g) * SMPAD + kb + 8 + 2 * cq];
            }
#pragma unroll
            for (int mi = 0; mi < 2; mi++)
#pragma unroll
                for (int ni = 0; ni < 8; ni++)
                    mma16816(acc[mi][ni], afr[mi], bfr[ni]);
        }
        __syncthreads();
    }

    // epilogue: thread owns rows {rb+g, rb+g+8}, cols nb+2cq,+1 per (mi,ni)
#pragma unroll
    for (int mi = 0; mi < 2; mi++) {
#pragma unroll
        for (int half = 0; half < 2; half++) {
            const int m = m0 + wm * 32 + mi * 16 + g + half * 8;
#pragma unroll
            for (int ni = 0; ni < 8; ni++) {
                const int n = n0 + wn * 64 + ni * 8 + 2 * cq;
                float2 bv = *(const float2*)(bias + n);
                float v0 = acc[mi][ni][half * 2 + 0] + bv.x;
                float v1 = acc[mi][ni][half * 2 + 1] + bv.y;
                if (EP == 2) {
                    v0 = fmaxf(v0, 0.f); v1 = fmaxf(v1, 0.f);
                    __nv_bfloat16 h0, h1, l0, l1;
                    split_bf16(v0, h0, l0); split_bf16(v1, h1, l1);
                    uint32_t hp, lp;
                    *(__nv_bfloat162*)&hp = __halves2bfloat162(h0, h1);
                    *(__nv_bfloat162*)&lp = __halves2bfloat162(l0, l1);
                    size_t rb = (size_t)m * 3 * N;
                    *(uint32_t*)(Cb + rb + n)         = hp;
                    *(uint32_t*)(Cb + rb + N + n)     = hp;
                    *(uint32_t*)(Cb + rb + 2 * N + n) = lp;
                } else {
                    if (EP == 1) {
                        float2 rv = *(const float2*)(res + (size_t)m * N + n);
                        v0 += rv.x; v1 += rv.y;
                    }
                    float2 o = make_float2(v0, v1);
                    *(float2*)(Cf + (size_t)m * N + n) = o;
                }
            }
        }
    }
}

// ---------------------------------------------------------------------------
// LayerNorm over rows of 512; optionally also writes split-bf16 (A-style)
// ---------------------------------------------------------------------------
template<bool CVT>
__global__ __launch_bounds__(128) void ln_kernel(
    const float* __restrict__ X, const float* __restrict__ gamma,
    const float* __restrict__ beta, float* __restrict__ O,
    __nv_bfloat16* __restrict__ Ocvt)
{
    __shared__ float red[4];
    const int row = blockIdx.x;
    const int tid = threadIdx.x;

    float4 v = *(const float4*)(X + (size_t)row * NU + tid * 4);
    float s = v.x + v.y + v.z + v.w;
#pragma unroll
    for (int o = 16; o > 0; o >>= 1) s += __shfl_xor_sync(0xffffffffu, s, o);
    if ((tid & 31) == 0) red[tid >> 5] = s;
    __syncthreads();
    float mean = (red[0] + red[1] + red[2] + red[3]) * (1.0f / 512.0f);
    __syncthreads();

    float dx = v.x - mean, dy = v.y - mean, dz = v.z - mean, dw = v.w - mean;
    float sq = dx * dx + dy * dy + dz * dz + dw * dw;
#pragma unroll
    for (int o = 16; o > 0; o >>= 1) sq += __shfl_xor_sync(0xffffffffu, sq, o);
    if ((tid & 31) == 0) red[tid >> 5] = sq;
    __syncthreads();
    float var = (red[0] + red[1] + red[2] + red[3]) * (1.0f / 512.0f);
    float inv = rsqrtf(var + 1e-5f);

    float4 g = *(const float4*)(gamma + tid * 4);
    float4 b = *(const float4*)(beta  + tid * 4);
    float4 o4;
    o4.x = dx * inv * g.x + b.x;
    o4.y = dy * inv * g.y + b.y;
    o4.z = dz * inv * g.z + b.z;
    o4.w = dw * inv * g.w + b.w;
    *(float4*)(O + (size_t)row * NU + tid * 4) = o4;

    if (CVT) {
        __nv_bfloat16 h0, h1, h2, h3, l0, l1, l2, l3;
        split_bf16(o4.x, h0, l0); split_bf16(o4.y, h1, l1);
        split_bf16(o4.z, h2, l2); split_bf16(o4.w, h3, l3);
        uint2 hp, lp;
        *(__nv_bfloat162*)&hp.x = __halves2bfloat162(h0, h1);
        *(__nv_bfloat162*)&hp.y = __halves2bfloat162(h2, h3);
        *(__nv_bfloat162*)&lp.x = __halves2bfloat162(l0, l1);
        *(__nv_bfloat162*)&lp.y = __halves2bfloat162(l2, l3);
        size_t rb = (size_t)row * (3 * NU);
        int col = tid * 4;
        *(uint2*)(Ocvt + rb + col)            = hp;
        *(uint2*)(Ocvt + rb + NU + col)       = hp;
        *(uint2*)(Ocvt + rb + 2 * NU + col)   = lp;
    }
}

// ---------------------------------------------------------------------------
// Attention (SIMT fp32): 8 query rows per block; writes ctx as split-bf16
// ---------------------------------------------------------------------------
__global__ __launch_bounds__(128) void attn_kernel(
    const float* __restrict__ Q, const float* __restrict__ K,
    const float* __restrict__ V, __nv_bfloat16* __restrict__ Ocvt)
{
    __shared__ float Ss[8][1024];
    __shared__ float KVs[32][68];
    __shared__ float rowsum[8];

    const int tid = threadIdx.x;
    const int qt = blockIdx.x;
    const int h  = blockIdx.y;
    const int b  = blockIdx.z;
    const int qr = tid >> 4;
    const int sl = tid & 15;

    const size_t base = ((size_t)b * SEQ) * NU + (size_t)h * DK;

    float4 qreg[16];
    {
        const float* qp = Q + base + (size_t)(qt * 8 + qr) * NU;
#pragma unroll
        for (int i = 0; i < 16; i++) qreg[i] = *(const float4*)(qp + i * 4);
    }

    for (int st = 0; st < 32; st++) {
        int s0 = st * 32;
#pragma unroll
        for (int i = 0; i < 4; i++) {
            int idx = tid + i * 128;
            int r   = idx >> 4;
            int c4  = (idx & 15) * 4;
            *(float4*)&KVs[r][c4] =
                *(const float4*)(K + base + (size_t)(s0 + r) * NU + c4);
        }
        __syncthreads();
#pragma unroll
        for (int ss = 0; ss < 2; ss++) {
            int s = sl + ss * 16;
            float a = 0.0f;
#pragma unroll
            for (int i = 0; i < 16; i++) {
                float4 kk = *(const float4*)&KVs[s][i * 4];
                a += qreg[i].x * kk.x + qreg[i].y * kk.y
                   + qreg[i].z * kk.z + qreg[i].w * kk.w;
            }
            Ss[qr][s0 + s] = a * 0.125f;
        }
        __syncthreads();
    }

    {
        const int warp = tid >> 5, lane = tid & 31;
        for (int r = warp; r < 8; r += 4) {
            float m = -1e30f;
            for (int j = lane; j < 1024; j += 32) m = fmaxf(m, Ss[r][j]);
#pragma unroll
            for (int o = 16; o > 0; o >>= 1)
                m = fmaxf(m, __shfl_xor_sync(0xffffffffu, m, o));
            float sum = 0.0f;
            for (int j = lane; j < 1024; j += 32) {
                float p = __expf(Ss[r][j] - m);
                Ss[r][j] = p;
                sum += p;
            }
#pragma unroll
            for (int o = 16; o > 0; o >>= 1)
                sum += __shfl_xor_sync(0xffffffffu, sum, o);
            if (lane == 0) rowsum[r] = sum;
        }
    }
    __syncthreads();

    const int d0 = (tid & 15) * 4;
    float4 acc = make_float4(0.f, 0.f, 0.f, 0.f);
    for (int st = 0; st < 32; st++) {
        int s0 = st * 32;
#pragma unroll
        for (int i = 0; i < 4; i++) {
            int idx = tid + i * 128;
            int r   = idx >> 4;
            int c4  = (idx & 15) * 4;
            *(float4*)&KVs[r][c4] =
                *(const float4*)(V + base + (size_t)(s0 + r) * NU + c4);
        }
        __syncthreads();
#pragma unroll
        for (int s = 0; s < 32; s++) {
            float p = Ss[qr][s0 + s];
            float4 vv = *(const float4*)&KVs[s][d0];
            acc.x += p * vv.x; acc.y += p * vv.y;
            acc.z += p * vv.z; acc.w += p * vv.w;
        }
        __syncthreads();
    }

    float inv = 1.0f / rowsum[qr];
    float v0 = acc.x * inv, v1 = acc.y * inv, v2 = acc.z * inv, v3 = acc.w * inv;

    __nv_bfloat16 h0, h1, h2, h3, l0, l1, l2, l3;
    split_bf16(v0, h0, l0); split_bf16(v1, h1, l1);
    split_bf16(v2, h2, l2); split_bf16(v3, h3, l3);
    uint2 hp, lp;
    *(__nv_bfloat162*)&hp.x = __halves2bfloat162(h0, h1);
    *(__nv_bfloat162*)&hp.y = __halves2bfloat162(h2, h3);
    *(__nv_bfloat162*)&lp.x = __halves2bfloat162(l0, l1);
    *(__nv_bfloat162*)&lp.y = __halves2bfloat162(l2, l3);

    size_t rb = (size_t)(b * SEQ + qt * 8 + qr) * (3 * NU);
    int col = h * DK + d0;
    *(uint2*)(Ocvt + rb + col)          = hp;
    *(uint2*)(Ocvt + rb + NU + col)     = hp;
    *(uint2*)(Ocvt + rb + 2 * NU + col) = lp;
}

// ---------------------------------------------------------------------------
// Host orchestration (graph-capturable: kernel launches only)
// ---------------------------------------------------------------------------
extern "C" void kernel_launch(void* const* d_in, const int* in_sizes, int n_in,
                              void* d_out, int out_size)
{
    (void)in_sizes; (void)n_in; (void)out_size;

    const float* x     = (const float*)d_in[0];
    const float* Win   = (const float*)d_in[1];
    const float* bin   = (const float*)d_in[2];
    const float* ln1_g = (const float*)d_in[3];
    const float* ln1_b = (const float*)d_in[4];
    const float* Wq    = (const float*)d_in[5];
    const float* bq    = (const float*)d_in[6];
    const float* Wk    = (const float*)d_in[7];
    const float* bk    = (const float*)d_in[8];
    const float* Wv    = (const float*)d_in[9];
    const float* bv    = (const float*)d_in[10];
    const float* Wo    = (const float*)d_in[11];
    const float* bo    = (const float*)d_in[12];
    const float* ln2_g = (const float*)d_in[13];
    const float* ln2_b = (const float*)d_in[14];
    const float* W1    = (const float*)d_in[15];
    const float* b1    = (const float*)d_in[16];
    const float* W2    = (const float*)d_in[17];
    const float* b2    = (const float*)d_in[18];
    const float* lno_g = (const float*)d_in[19];
    const float* lno_b = (const float*)d_in[20];
    float* out = (float*)d_out;

    float *e, *q, *k, *v;
    __nv_bfloat16 *xc, *ec, *cc, *hc, *Winc, *Wqc, *Wkc, *Wvc, *Woc, *W1c, *W2c;
    cudaGetSymbolAddress((void**)&e,   g_e);
    cudaGetSymbolAddress((void**)&q,   g_q);
    cudaGetSymbolAddress((void**)&k,   g_k);
    cudaGetSymbolAddress((void**)&v,   g_v);
    cudaGetSymbolAddress((void**)&xc,  g_xcvt);
    cudaGetSymbolAddress((void**)&ec,  g_ecvt);
    cudaGetSymbolAddress((void**)&cc,  g_ccvt);
    cudaGetSymbolAddress((void**)&hc,  g_hcvt);
    cudaGetSymbolAddress((void**)&Winc, g_Winc);
    cudaGetSymbolAddress((void**)&Wqc, g_Wqc);
    cudaGetSymbolAddress((void**)&Wkc, g_Wkc);
    cudaGetSymbolAddress((void**)&Wvc, g_Wvc);
    cudaGetSymbolAddress((void**)&Woc, g_Woc);
    cudaGetSymbolAddress((void**)&W1c, g_W1c);
    cudaGetSymbolAddress((void**)&W2c, g_W2c);

    // operand conversions (every launch; deterministic)
    {
        int t;
        t = NU * IDIM;              convert_B_kernel<<<(t + 255) / 256, 256>>>(Win, Winc, IDIM, t);
        t = NLAYERS * NU * NU;      convert_B_kernel<<<(t + 255) / 256, 256>>>(Wq, Wqc, NU, t);
                                    convert_B_kernel<<<(t + 255) / 256, 256>>>(Wk, Wkc, NU, t);
                                    convert_B_kernel<<<(t + 255) / 256, 256>>>(Wv, Wvc, NU, t);
                                    convert_B_kernel<<<(t + 255) / 256, 256>>>(Wo, Woc, NU, t);
        t = NLAYERS * EU * NU;      convert_B_kernel<<<(t + 255) / 256, 256>>>(W1, W1c, NU, t);
        t = NLAYERS * NU * EU;      convert_B_kernel<<<(t + 255) / 256, 256>>>(W2, W2c, EU, t);
        t = TOK * IDIM;             convert_A_kernel<<<(t + 255) / 256, 256>>>(x, xc, IDIM, t);
    }

    dim3 g512(NU / 128, TOK / 128);     // (4, 64)
    dim3 g2048(EU / 128, TOK / 128);    // (16, 64)
    dim3 gattn(SEQ / 8, HEADS, NBATCH);

    // input projection: e = x @ Win^T + bin
    mma_gemm<0><<<g512, 256>>>(xc, Winc, bin, nullptr, e, nullptr, NU, 3 * IDIM);

    for (int i = 0; i < NLAYERS; i++) {
        const size_t wo  = (size_t)i * NU * 3 * NU;
        const size_t w1o = (size_t)i * EU * 3 * NU;
        const size_t w2o = (size_t)i * NU * 3 * EU;

        ln_kernel<true><<<TOK, 128>>>(e, ln1_g + i * NU, ln1_b + i * NU, e, ec);

        mma_gemm<0><<<g512, 256>>>(ec, Wqc + wo, bq + i * NU, nullptr, q, nullptr, NU, 3 * NU);
        mma_gemm<0><<<g512, 256>>>(ec, Wkc + wo, bk + i * NU, nullptr, k, nullptr, NU, 3 * NU);
        mma_gemm<0><<<g512, 256>>>(ec, Wvc + wo, bv + i * NU, nullptr, v, nullptr, NU, 3 * NU);

        attn_kernel<<<gattn, 128>>>(q, k, v, cc);

        // e = e + ctx @ Wo^T + bo
        mma_gemm<1><<<g512, 256>>>(cc, Woc + wo, bo + i * NU, e, e, nullptr, NU, 3 * NU);

        ln_kernel<true><<<TOK, 128>>>(e, ln2_g + i * NU, ln2_b + i * NU, e, ec);

        // h = relu(e @ W1^T + b1) -> split bf16
        mma_gemm<2><<<g2048, 256>>>(ec, W1c + w1o, b1 + (size_t)i * EU, nullptr,
                                    nullptr, hc, EU, 3 * NU);
        // e = e + h @ W2^T + b2
        mma_gemm<1><<<g512, 256>>>(hc, W2c + w2o, b2 + i * NU, e, e, nullptr, NU, 3 * EU);
    }

    ln_kernel<false><<<TOK, 128>>>(e, lno_g, lno_b, out, nullptr);
}

// round 8
// speedup vs baseline: 1.4684x; 1.3171x over previous
#include <cuda_runtime.h>
#include <cuda_bf16.h>
#include <math.h>
#include <stdint.h>

// ---------------------------------------------------------------------------
// Problem constants
// ---------------------------------------------------------------------------
#define TOK      8192
#define IDIM     256
#define NU       512
#define EU       2048
#define NLAYERS  4
#define HEADS    8
#define DK       64
#define SEQ      1024
#define NBATCH   8
#define QKVW     1536      // fused q|k|v row width

// ---------------------------------------------------------------------------
// Scratch (static device memory; allocation APIs are forbidden)
// ---------------------------------------------------------------------------
__device__ float g_e  [TOK * NU];
__device__ float g_qkv[TOK * QKVW];

// split-bf16 operand buffers (K-concat: activations [hi|hi|lo], weights [hi|lo|hi])
__device__ __nv_bfloat16 g_xcvt [TOK * 3 * IDIM];
__device__ __nv_bfloat16 g_ecvt [TOK * 3 * NU];
__device__ __nv_bfloat16 g_ccvt [TOK * 3 * NU];
__device__ __nv_bfloat16 g_hcvt [TOK * 3 * EU];

__device__ __nv_bfloat16 g_Winc  [NU * 3 * IDIM];
__device__ __nv_bfloat16 g_Wqkvc [NLAYERS * QKVW * 3 * NU];
__device__ __nv_bfloat16 g_Woc   [NLAYERS * NU * 3 * NU];
__device__ __nv_bfloat16 g_W1c   [NLAYERS * EU * 3 * NU];
__device__ __nv_bfloat16 g_W2c   [NLAYERS * NU * 3 * EU];
__device__ float         g_bqkv  [NLAYERS * QKVW];

// ---------------------------------------------------------------------------
// split helpers
// ---------------------------------------------------------------------------
__device__ __forceinline__ void split_bf16(float f, __nv_bfloat16& hi, __nv_bfloat16& lo) {
    hi = __float2bfloat16(f);
    lo = __float2bfloat16(f - __bfloat162float(hi));
}

// weights: out row = [hi | lo | hi], row width 3K
__global__ void convert_B_kernel(const float* __restrict__ W, __nv_bfloat16* __restrict__ out,
                                 int K, int total) {
    int idx = blockIdx.x * 256 + threadIdx.x;
    if (idx >= total) return;
    int n = idx / K, k = idx - n * K;
    __nv_bfloat16 hi, lo;
    split_bf16(W[idx], hi, lo);
    size_t base = (size_t)n * 3 * K;
    out[base + k] = hi;
    out[base + K + k] = lo;
    out[base + 2 * K + k] = hi;
}

// activations: out row = [hi | hi | lo]
__global__ void convert_A_kernel(const float* __restrict__ A, __nv_bfloat16* __restrict__ out,
                                 int K, int total) {
    int idx = blockIdx.x * 256 + threadIdx.x;
    if (idx >= total) return;
    int n = idx / K, k = idx - n * K;
    __nv_bfloat16 hi, lo;
    split_bf16(A[idx], hi, lo);
    size_t base = (size_t)n * 3 * K;
    out[base + k] = hi;
    out[base + K + k] = hi;
    out[base + 2 * K + k] = lo;
}

// pack per-layer q|k|v biases into 1536-wide rows
__global__ void pack_bqkv_kernel(const float* __restrict__ bq, const float* __restrict__ bk,
                                 const float* __restrict__ bv, float* __restrict__ out) {
    int i = blockIdx.x * 256 + threadIdx.x;
    if (i >= NLAYERS * QKVW) return;
    int l = i / QKVW, c = i - l * QKVW;
    float v = (c < NU) ? bq[l * NU + c]
            : (c < 2 * NU) ? bk[l * NU + c - NU]
            : bv[l * NU + c - 2 * NU];
    out[i] = v;
}

// ---------------------------------------------------------------------------
// mma.sync bf16 GEMM with cp.async double buffering + ldmatrix.
// C[M,N] = A[M,Kp] @ B[N,Kp]^T (+bias, +opt residual / relu+split-cvt)
// 128x128 CTA tile, 256 threads (8 warps 4x2), warp tile 32x64, K-chunk 64.
// smem: XOR-swizzled 128B rows (16B block ^ (row&7)), 2 stages x (16KB A + 16KB B).
// EP: 0 = fp32 out, 1 = fp32 out + residual, 2 = relu + split-bf16 out (A-style)
// ---------------------------------------------------------------------------
#define STAGE_BYTES 32768
#define GEMM_DSMEM  (2 * STAGE_BYTES)

__device__ __forceinline__ uint32_t smem_u32(const void* p) {
    uint32_t a;
    asm("{ .reg .u64 t; cvta.to.shared.u64 t, %1; cvt.u32.u64 %0, t; }" : "=r"(a) : "l"(p));
    return a;
}

#define CP_ASYNC16(dst, src) \
    asm volatile("cp.async.cg.shared.global [%0], [%1], 16;" :: "r"(dst), "l"(src) : "memory")
#define CP_COMMIT() asm volatile("cp.async.commit_group;" ::: "memory")
#define CP_WAIT1()  asm volatile("cp.async.wait_group 1;" ::: "memory")

#define LDMATRIX_X4(r0, r1, r2, r3, addr) \
    asm volatile("ldmatrix.sync.aligned.m8n8.x4.shared.b16 {%0,%1,%2,%3}, [%4];" \
        : "=r"(r0), "=r"(r1), "=r"(r2), "=r"(r3) : "r"(addr))

__device__ __forceinline__ void mma16816(float* d, const uint32_t* a, const uint32_t* b) {
    asm volatile(
        "mma.sync.aligned.m16n8k16.row.col.f32.bf16.bf16.f32 "
        "{%0,%1,%2,%3}, {%4,%5,%6,%7}, {%8,%9}, {%0,%1,%2,%3};"
        : "+f"(d[0]), "+f"(d[1]), "+f"(d[2]), "+f"(d[3])
        : "r"(a[0]), "r"(a[1]), "r"(a[2]), "r"(a[3]), "r"(b[0]), "r"(b[1]));
}

template<int EP>
__global__ __launch_bounds__(256) void mma_gemm(
    const __nv_bfloat16* __restrict__ A, const __nv_bfloat16* __restrict__ B,
    const float* __restrict__ bias, const float* __restrict__ res,
    float* __restrict__ Cf, __nv_bfloat16* __restrict__ Cb,
    int N, int Kp)
{
    extern __shared__ __align__(16) char dsm[];
    const uint32_t sbase = smem_u32(dsm);

    const int tid  = threadIdx.x;
    const int wid  = tid >> 5;
    const int lane = tid & 31;
    const int g    = lane >> 2;      // 0..7
    const int cq   = lane & 3;       // 0..3
    const int lr   = lane & 15;      // ldmatrix row select
    const int lc   = lane >> 4;      // ldmatrix col-block select (0/1)
    const int wm   = wid & 3;        // warp m (0..3) -> 32 rows
    const int wn   = wid >> 2;       // warp n (0..1) -> 64 cols
    const int n0   = blockIdx.x * 128;
    const int m0   = blockIdx.y * 128;

    const __nv_bfloat16* Ap = A + (size_t)m0 * Kp;
    const __nv_bfloat16* Bp = B + (size_t)n0 * Kp;

    // per-thread cp.async source/dest precomputation (4 chunks of A + 4 of B)
    // lin = tid + i*256 -> r = lin>>3 (0..127), c16 = lin&7
    const int nchunk = Kp >> 6;

    float acc[2][8][4];
#pragma unroll
    for (int mi = 0; mi < 2; mi++)
#pragma unroll
        for (int ni = 0; ni < 8; ni++)
#pragma unroll
            for (int r = 0; r < 4; r++) acc[mi][ni][r] = 0.0f;

    // ---- async tile loader ----
    auto load_stage = [&](int c, int stage) {
        const int k0 = c << 6;
        const uint32_t sA = sbase + stage * STAGE_BYTES;
        const uint32_t sB = sA + 16384;
#pragma unroll
        for (int i = 0; i < 4; i++) {
            int lin = tid + i * 256;
            int r   = lin >> 3;
            int c16 = lin & 7;
            uint32_t off = (uint32_t)(r * 128 + ((c16 ^ (r & 7)) * 16));
            CP_ASYNC16(sA + off, (const void*)(Ap + (size_t)r * Kp + k0 + c16 * 8));
            CP_ASYNC16(sB + off, (const void*)(Bp + (size_t)r * Kp + k0 + c16 * 8));
        }
    };

    load_stage(0, 0);
    CP_COMMIT();

    for (int c = 0; c < nchunk; c++) {
        const int cur = c & 1;
        if (c + 1 < nchunk) load_stage(c + 1, cur ^ 1);
        CP_COMMIT();
        CP_WAIT1();
        __syncthreads();

        const uint32_t sA = sbase + cur * STAGE_BYTES;
        const uint32_t sB = sA + 16384;

#pragma unroll
        for (int ks = 0; ks < 4; ks++) {
            const int kblk = ks * 2 + lc;       // 16B block within 128B row
            uint32_t afr[2][4], bfr[4][4];
#pragma unroll
            for (int mi = 0; mi < 2; mi++) {
                int row = wm * 32 + mi * 16 + lr;
                uint32_t addr = sA + (uint32_t)(row * 128 + ((kblk ^ (row & 7)) * 16));
                LDMATRIX_X4(afr[mi][0], afr[mi][1], afr[mi][2], afr[mi][3], addr);
            }
#pragma unroll
            for (int p = 0; p < 4; p++) {
                int row = wn * 64 + p * 16 + lr;
                uint32_t addr = sB + (uint32_t)(row * 128 + ((kblk ^ (row & 7)) * 16));
                LDMATRIX_X4(bfr[p][0], bfr[p][1], bfr[p][2], bfr[p][3], addr);
            }
#pragma unroll
            for (int mi = 0; mi < 2; mi++)
#pragma unroll
                for (int ni = 0; ni < 8; ni++) {
                    const int p = ni >> 1, o = ni & 1;
                    uint32_t b2[2] = { bfr[p][o], bfr[p][2 + o] };
                    mma16816(acc[mi][ni], afr[mi], b2);
                }
        }
        __syncthreads();
    }

    // epilogue: thread owns rows {rb+g, rb+g+8}, cols nb+2cq..+1 per (mi,ni)
#pragma unroll
    for (int mi = 0; mi < 2; mi++) {
#pragma unroll
        for (int half = 0; half < 2; half++) {
            const int m = m0 + wm * 32 + mi * 16 + g + half * 8;
#pragma unroll
            for (int ni = 0; ni < 8; ni++) {
                const int n = n0 + wn * 64 + ni * 8 + 2 * cq;
                float2 bv = *(const float2*)(bias + n);
                float v0 = acc[mi][ni][half * 2 + 0] + bv.x;
                float v1 = acc[mi][ni][half * 2 + 1] + bv.y;
                if (EP == 2) {
                    v0 = fmaxf(v0, 0.f); v1 = fmaxf(v1, 0.f);
                    __nv_bfloat16 h0, h1, l0, l1;
                    split_bf16(v0, h0, l0); split_bf16(v1, h1, l1);
                    uint32_t hp, lp;
                    *(__nv_bfloat162*)&hp = __halves2bfloat162(h0, h1);
                    *(__nv_bfloat162*)&lp = __halves2bfloat162(l0, l1);
                    size_t rb = (size_t)m * 3 * N;
                    *(uint32_t*)(Cb + rb + n)         = hp;
                    *(uint32_t*)(Cb + rb + N + n)     = hp;
                    *(uint32_t*)(Cb + rb + 2 * N + n) = lp;
                } else {
                    if (EP == 1) {
                        float2 rv = *(const float2*)(res + (size_t)m * N + n);
                        v0 += rv.x; v1 += rv.y;
                    }
                    *(float2*)(Cf + (size_t)m * N + n) = make_float2(v0, v1);
                }
            }
        }
    }
}

// ---------------------------------------------------------------------------
// LayerNorm over rows of 512; optionally also writes split-bf16 (A-style)
// ---------------------------------------------------------------------------
template<bool CVT>
__global__ __launch_bounds__(128) void ln_kernel(
    const float* __restrict__ X, const float* __restrict__ gamma,
    const float* __restrict__ beta, float* __restrict__ O,
    __nv_bfloat16* __restrict__ Ocvt)
{
    __shared__ float red[4];
    const int row = blockIdx.x;
    const int tid = threadIdx.x;

    float4 v = *(const float4*)(X + (size_t)row * NU + tid * 4);
    float s = v.x + v.y + v.z + v.w;
#pragma unroll
    for (int o = 16; o > 0; o >>= 1) s += __shfl_xor_sync(0xffffffffu, s, o);
    if ((tid & 31) == 0) red[tid >> 5] = s;
    __syncthreads();
    float mean = (red[0] + red[1] + red[2] + red[3]) * (1.0f / 512.0f);
    __syncthreads();

    float dx = v.x - mean, dy = v.y - mean, dz = v.z - mean, dw = v.w - mean;
    float sq = dx * dx + dy * dy + dz * dz + dw * dw;
#pragma unroll
    for (int o = 16; o > 0; o >>= 1) sq += __shfl_xor_sync(0xffffffffu, sq, o);
    if ((tid & 31) == 0) red[tid >> 5] = sq;
    __syncthreads();
    float var = (red[0] + red[1] + red[2] + red[3]) * (1.0f / 512.0f);
    float inv = rsqrtf(var + 1e-5f);

    float4 g = *(const float4*)(gamma + tid * 4);
    float4 b = *(const float4*)(beta  + tid * 4);
    float4 o4;
    o4.x = dx * inv * g.x + b.x;
    o4.y = dy * inv * g.y + b.y;
    o4.z = dz * inv * g.z + b.z;
    o4.w = dw * inv * g.w + b.w;
    *(float4*)(O + (size_t)row * NU + tid * 4) = o4;

    if (CVT) {
        __nv_bfloat16 h0, h1, h2, h3, l0, l1, l2, l3;
        split_bf16(o4.x, h0, l0); split_bf16(o4.y, h1, l1);
        split_bf16(o4.z, h2, l2); split_bf16(o4.w, h3, l3);
        uint2 hp, lp;
        *(__nv_bfloat162*)&hp.x = __halves2bfloat162(h0, h1);
        *(__nv_bfloat162*)&hp.y = __halves2bfloat162(h2, h3);
        *(__nv_bfloat162*)&lp.x = __halves2bfloat162(l0, l1);
        *(__nv_bfloat162*)&lp.y = __halves2bfloat162(l2, l3);
        size_t rb = (size_t)row * (3 * NU);
        int col = tid * 4;
        *(uint2*)(Ocvt + rb + col)            = hp;
        *(uint2*)(Ocvt + rb + NU + col)       = hp;
        *(uint2*)(Ocvt + rb + 2 * NU + col)   = lp;
    }
}

// ---------------------------------------------------------------------------
// Attention (SIMT fp32): reads fused qkv rows (width 1536: q|k|v);
// writes ctx as split-bf16. 8 query rows per block.
// ---------------------------------------------------------------------------
__global__ __launch_bounds__(128) void attn_kernel(
    const float* __restrict__ QKV, __nv_bfloat16* __restrict__ Ocvt)
{
    __shared__ float Ss[8][1024];
    __shared__ float KVs[32][68];
    __shared__ float rowsum[8];

    const int tid = threadIdx.x;
    const int qt = blockIdx.x;
    const int h  = blockIdx.y;
    const int b  = blockIdx.z;
    const int qr = tid >> 4;
    const int sl = tid & 15;

    const size_t rowbase = (size_t)b * SEQ;
    const int hoff = h * DK;

    float4 qreg[16];
    {
        const float* qp = QKV + (rowbase + qt * 8 + qr) * QKVW + hoff;
#pragma unroll
        for (int i = 0; i < 16; i++) qreg[i] = *(const float4*)(qp + i * 4);
    }

    for (int st = 0; st < 32; st++) {
        int s0 = st * 32;
#pragma unroll
        for (int i = 0; i < 4; i++) {
            int idx = tid + i * 128;
            int r   = idx >> 4;
            int c4  = (idx & 15) * 4;
            *(float4*)&KVs[r][c4] =
                *(const float4*)(QKV + (rowbase + s0 + r) * QKVW + NU + hoff + c4);
        }
        __syncthreads();
#pragma unroll
        for (int ss = 0; ss < 2; ss++) {
            int s = sl + ss * 16;
            float a = 0.0f;
#pragma unroll
            for (int i = 0; i < 16; i++) {
                float4 kk = *(const float4*)&KVs[s][i * 4];
                a += qreg[i].x * kk.x + qreg[i].y * kk.y
                   + qreg[i].z * kk.z + qreg[i].w * kk.w;
            }
            Ss[qr][s0 + s] = a * 0.125f;
        }
        __syncthreads();
    }

    {
        const int warp = tid >> 5, lane = tid & 31;
        for (int r = warp; r < 8; r += 4) {
            float m = -1e30f;
            for (int j = lane; j < 1024; j += 32) m = fmaxf(m, Ss[r][j]);
#pragma unroll
            for (int o = 16; o > 0; o >>= 1)
                m = fmaxf(m, __shfl_xor_sync(0xffffffffu, m, o));
            float sum = 0.0f;
            for (int j = lane; j < 1024; j += 32) {
                float p = __expf(Ss[r][j] - m);
                Ss[r][j] = p;
                sum += p;
            }
#pragma unroll
            for (int o = 16; o > 0; o >>= 1)
                sum += __shfl_xor_sync(0xffffffffu, sum, o);
            if (lane == 0) rowsum[r] = sum;
        }
    }
    __syncthreads();

    const int d0 = (tid & 15) * 4;
    float4 acc = make_float4(0.f, 0.f, 0.f, 0.f);
    for (int st = 0; st < 32; st++) {
        int s0 = st * 32;
#pragma unroll
        for (int i = 0; i < 4; i++) {
            int idx = tid + i * 128;
            int r   = idx >> 4;
            int c4  = (idx & 15) * 4;
            *(float4*)&KVs[r][c4] =
                *(const float4*)(QKV + (rowbase + s0 + r) * QKVW + 2 * NU + hoff + c4);
        }
        __syncthreads();
#pragma unroll
        for (int s = 0; s < 32; s++) {
            float p = Ss[qr][s0 + s];
            float4 vv = *(const float4*)&KVs[s][d0];
            acc.x += p * vv.x; acc.y += p * vv.y;
            acc.z += p * vv.z; acc.w += p * vv.w;
        }
        __syncthreads();
    }

    float inv = 1.0f / rowsum[qr];
    float v0 = acc.x * inv, v1 = acc.y * inv, v2 = acc.z * inv, v3 = acc.w * inv;

    __nv_bfloat16 h0, h1, h2, h3, l0, l1, l2, l3;
    split_bf16(v0, h0, l0); split_bf16(v1, h1, l1);
    split_bf16(v2, h2, l2); split_bf16(v3, h3, l3);
    uint2 hp, lp;
    *(__nv_bfloat162*)&hp.x = __halves2bfloat162(h0, h1);
    *(__nv_bfloat162*)&hp.y = __halves2bfloat162(h2, h3);
    *(__nv_bfloat162*)&lp.x = __halves2bfloat162(l0, l1);
    *(__nv_bfloat162*)&lp.y = __halves2bfloat162(l2, l3);

    size_t rb = (size_t)(b * SEQ + qt * 8 + qr) * (3 * NU);
    int col = hoff + d0;
    *(uint2*)(Ocvt + rb + col)          = hp;
    *(uint2*)(Ocvt + rb + NU + col)     = hp;
    *(uint2*)(Ocvt + rb + 2 * NU + col) = lp;
}

// ---------------------------------------------------------------------------
// Host orchestration (graph-capturable: kernel launches only)
// ---------------------------------------------------------------------------
extern "C" void kernel_launch(void* const* d_in, const int* in_sizes, int n_in,
                              void* d_out, int out_size)
{
    (void)in_sizes; (void)n_in; (void)out_size;

    const float* x     = (const float*)d_in[0];
    const float* Win   = (const float*)d_in[1];
    const float* bin   = (const float*)d_in[2];
    const float* ln1_g = (const float*)d_in[3];
    const float* ln1_b = (const float*)d_in[4];
    const float* Wq    = (const float*)d_in[5];
    const float* bq    = (const float*)d_in[6];
    const float* Wk    = (const float*)d_in[7];
    const float* bk    = (const float*)d_in[8];
    const float* Wv    = (const float*)d_in[9];
    const float* bv    = (const float*)d_in[10];
    const float* Wo    = (const float*)d_in[11];
    const float* bo    = (const float*)d_in[12];
    const float* ln2_g = (const float*)d_in[13];
    const float* ln2_b = (const float*)d_in[14];
    const float* W1    = (const float*)d_in[15];
    const float* b1    = (const float*)d_in[16];
    const float* W2    = (const float*)d_in[17];
    const float* b2    = (const float*)d_in[18];
    const float* lno_g = (const float*)d_in[19];
    const float* lno_b = (const float*)d_in[20];
    float* out = (float*)d_out;

    float *e, *qkv, *bqkv;
    __nv_bfloat16 *xc, *ec, *cc, *hc, *Winc, *Wqkvc, *Woc, *W1c, *W2c;
    cudaGetSymbolAddress((void**)&e,    g_e);
    cudaGetSymbolAddress((void**)&qkv,  g_qkv);
    cudaGetSymbolAddress((void**)&bqkv, g_bqkv);
    cudaGetSymbolAddress((void**)&xc,   g_xcvt);
    cudaGetSymbolAddress((void**)&ec,   g_ecvt);
    cudaGetSymbolAddress((void**)&cc,   g_ccvt);
    cudaGetSymbolAddress((void**)&hc,   g_hcvt);
    cudaGetSymbolAddress((void**)&Winc,  g_Winc);
    cudaGetSymbolAddress((void**)&Wqkvc, g_Wqkvc);
    cudaGetSymbolAddress((void**)&Woc,   g_Woc);
    cudaGetSymbolAddress((void**)&W1c,   g_W1c);
    cudaGetSymbolAddress((void**)&W2c,   g_W2c);

    // allow 64KB dynamic smem on the GEMM (idempotent)
    cudaFuncSetAttribute(mma_gemm<0>, cudaFuncAttributeMaxDynamicSharedMemorySize, GEMM_DSMEM);
    cudaFuncSetAttribute(mma_gemm<1>, cudaFuncAttributeMaxDynamicSharedMemorySize, GEMM_DSMEM);
    cudaFuncSetAttribute(mma_gemm<2>, cudaFuncAttributeMaxDynamicSharedMemorySize, GEMM_DSMEM);

    // operand conversions (every launch; deterministic)
    {
        int t;
        t = NU * IDIM;          convert_B_kernel<<<(t + 255) / 256, 256>>>(Win, Winc, IDIM, t);
        t = NLAYERS * NU * NU;  // each section of the fused qkv weight
        for (int i = 0; i < NLAYERS; i++) {
            const size_t lb = (size_t)i * QKVW * 3 * NU;
            int tt = NU * NU;
            convert_B_kernel<<<(tt + 255) / 256, 256>>>(Wq + (size_t)i * NU * NU, Wqkvc + lb, NU, tt);
            convert_B_kernel<<<(tt + 255) / 256, 256>>>(Wk + (size_t)i * NU * NU, Wqkvc + lb + (size_t)NU * 3 * NU, NU, tt);
            convert_B_kernel<<<(tt + 255) / 256, 256>>>(Wv + (size_t)i * NU * NU, Wqkvc + lb + (size_t)2 * NU * 3 * NU, NU, tt);
        }
        t = NLAYERS * NU * NU;  convert_B_kernel<<<(t + 255) / 256, 256>>>(Wo, Woc, NU, t);
        t = NLAYERS * EU * NU;  convert_B_kernel<<<(t + 255) / 256, 256>>>(W1, W1c, NU, t);
        t = NLAYERS * NU * EU;  convert_B_kernel<<<(t + 255) / 256, 256>>>(W2, W2c, EU, t);
        t = TOK * IDIM;         convert_A_kernel<<<(t + 255) / 256, 256>>>(x, xc, IDIM, t);
        t = NLAYERS * QKVW;     pack_bqkv_kernel<<<(t + 255) / 256, 256>>>(bq, bk, bv, bqkv);
    }

    dim3 g512 (NU   / 128, TOK / 128);   // (4, 64)
    dim3 gqkv (QKVW / 128, TOK / 128);   // (12, 64)
    dim3 g2048(EU   / 128, TOK / 128);   // (16, 64)
    dim3 gattn(SEQ / 8, HEADS, NBATCH);

    // input projection: e = x @ Win^T + bin
    mma_gemm<0><<<g512, 256, GEMM_DSMEM>>>(xc, Winc, bin, nullptr, e, nullptr, NU, 3 * IDIM);

    for (int i = 0; i < NLAYERS; i++) {
        const size_t wqkv = (size_t)i * QKVW * 3 * NU;
        const size_t wo   = (size_t)i * NU * 3 * NU;
        const size_t w1o  = (size_t)i * EU * 3 * NU;
        const size_t w2o  = (size_t)i * NU * 3 * EU;

        ln_kernel<true><<<TOK, 128>>>(e, ln1_g + i * NU, ln1_b + i * NU, e, ec);

        // fused qkv = ln(e) @ [Wq|Wk|Wv]^T + [bq|bk|bv]
        mma_gemm<0><<<gqkv, 256, GEMM_DSMEM>>>(ec, Wqkvc + wqkv, bqkv + i * QKVW, nullptr,
                                               qkv, nullptr, QKVW, 3 * NU);

        attn_kernel<<<gattn, 128>>>(qkv, cc);

        // e = e + ctx @ Wo^T + bo
        mma_gemm<1><<<g512, 256, GEMM_DSMEM>>>(cc, Woc + wo, bo + i * NU, e, e, nullptr, NU, 3 * NU);

        ln_kernel<true><<<TOK, 128>>>(e, ln2_g + i * NU, ln2_b + i * NU, e, ec);

        // h = relu(e @ W1^T + b1) -> split bf16
        mma_gemm<2><<<g2048, 256, GEMM_DSMEM>>>(ec, W1c + w1o, b1 + (size_t)i * EU, nullptr,
                                                nullptr, hc, EU, 3 * NU);
        // e = e + h @ W2^T + b2
        mma_gemm<1><<<g512, 256, GEMM_DSMEM>>>(hc, W2c + w2o, b2 + i * NU, e, e, nullptr, NU, 3 * EU);
    }

    ln_kernel<false><<<TOK, 128>>>(e, lno_g, lno_b, out, nullptr);
}

// round 9
// speedup vs baseline: 2.9760x; 2.0267x over previous
#include <cuda_runtime.h>
#include <cuda_bf16.h>
#include <math.h>
#include <stdint.h>

// ---------------------------------------------------------------------------
// Problem constants
// ---------------------------------------------------------------------------
#define TOK      8192
#define IDIM     256
#define NU       512
#define EU       2048
#define NLAYERS  4
#define HEADS    8
#define DK       64
#define SEQ      1024
#define NBATCH   8
#define QKVW     1536      // fused q|k|v row width
#define BH       (NBATCH * HEADS)   // 64
#define DKS      192       // split q/k K-width (3*64)
#define SS       3072      // split P/Vt K-width (3*1024)

// ---------------------------------------------------------------------------
// Scratch (static device memory; allocation APIs are forbidden)
// ---------------------------------------------------------------------------
__device__ float g_e  [TOK * NU];
__device__ float g_qkv[TOK * QKVW];

// split-bf16 operand buffers (K-concat: activations [hi|hi|lo], weights [hi|lo|hi])
__device__ __nv_bfloat16 g_xcvt [TOK * 3 * IDIM];
__device__ __nv_bfloat16 g_ecvt [TOK * 3 * NU];
__device__ __nv_bfloat16 g_ccvt [TOK * 3 * NU];
__device__ __nv_bfloat16 g_hcvt [TOK * 3 * EU];

__device__ __nv_bfloat16 g_Winc  [NU * 3 * IDIM];
__device__ __nv_bfloat16 g_Wqkvc [NLAYERS * QKVW * 3 * NU];
__device__ __nv_bfloat16 g_Woc   [NLAYERS * NU * 3 * NU];
__device__ __nv_bfloat16 g_W1c   [NLAYERS * EU * 3 * NU];
__device__ __nv_bfloat16 g_W2c   [NLAYERS * NU * 3 * EU];
__device__ float         g_bqkv  [NLAYERS * QKVW];

// attention scratch
__device__ __nv_bfloat16 g_qs [BH * SEQ * DKS];    // Q split (A-style), scaled
__device__ __nv_bfloat16 g_ks [BH * SEQ * DKS];    // K split (B-style)
__device__ __nv_bfloat16 g_vt [BH * DK * SS];      // V^T split (B-style over s)
__device__ float         g_sc [(size_t)BH * SEQ * SEQ];   // scores fp32
__device__ __nv_bfloat16 g_ps [(size_t)BH * SEQ * SS];    // P split (A-style)

// ---------------------------------------------------------------------------
// split helpers
// ---------------------------------------------------------------------------
__device__ __forceinline__ void split_bf16(float f, __nv_bfloat16& hi, __nv_bfloat16& lo) {
    hi = __float2bfloat16(f);
    lo = __float2bfloat16(f - __bfloat162float(hi));
}

// weights: out row = [hi | lo | hi], row width 3K
__global__ void convert_B_kernel(const float* __restrict__ W, __nv_bfloat16* __restrict__ out,
                                 int K, int total) {
    int idx = blockIdx.x * 256 + threadIdx.x;
    if (idx >= total) return;
    int n = idx / K, k = idx - n * K;
    __nv_bfloat16 hi, lo;
    split_bf16(W[idx], hi, lo);
    size_t base = (size_t)n * 3 * K;
    out[base + k] = hi;
    out[base + K + k] = lo;
    out[base + 2 * K + k] = hi;
}

// activations: out row = [hi | hi | lo]
__global__ void convert_A_kernel(const float* __restrict__ A, __nv_bfloat16* __restrict__ out,
                                 int K, int total) {
    int idx = blockIdx.x * 256 + threadIdx.x;
    if (idx >= total) return;
    int n = idx / K, k = idx - n * K;
    __nv_bfloat16 hi, lo;
    split_bf16(A[idx], hi, lo);
    size_t base = (size_t)n * 3 * K;
    out[base + k] = hi;
    out[base + K + k] = hi;
    out[base + 2 * K + k] = lo;
}

// pack per-layer q|k|v biases into 1536-wide rows
__global__ void pack_bqkv_kernel(const float* __restrict__ bq, const float* __restrict__ bk,
                                 const float* __restrict__ bv, float* __restrict__ out) {
    int i = blockIdx.x * 256 + threadIdx.x;
    if (i >= NLAYERS * QKVW) return;
    int l = i / QKVW, c = i - l * QKVW;
    float v = (c < NU) ? bq[l * NU + c]
            : (c < 2 * NU) ? bk[l * NU + c - NU]
            : bv[l * NU + c - 2 * NU];
    out[i] = v;
}

// slice fused qkv into per-head split operands.
// one thread per (bh, t, d4): 64*1024*16 threads; d = d4*4 .. d4*4+3
__global__ void convert_attn_kernel(const float* __restrict__ QKV,
    __nv_bfloat16* __restrict__ qs, __nv_bfloat16* __restrict__ ks,
    __nv_bfloat16* __restrict__ vt)
{
    int idx = blockIdx.x * 256 + threadIdx.x;
    if (idx >= BH * SEQ * 16) return;
    int d4 = idx & 15;
    int t  = (idx >> 4) & (SEQ - 1);
    int bh = idx >> 14;
    int b = bh >> 3, h = bh & 7;
    const float* row = QKV + (size_t)(b * SEQ + t) * QKVW + h * DK + d4 * 4;
    float4 qv = *(const float4*)(row);
    float4 kv = *(const float4*)(row + NU);
    float4 vv = *(const float4*)(row + 2 * NU);

    // Q: scale folded in, A-style [hi|hi|lo]
    {
        __nv_bfloat16 h0,h1,h2,h3,l0,l1,l2,l3;
        split_bf16(qv.x * 0.125f, h0, l0); split_bf16(qv.y * 0.125f, h1, l1);
        split_bf16(qv.z * 0.125f, h2, l2); split_bf16(qv.w * 0.125f, h3, l3);
        uint2 hp, lp;
        *(__nv_bfloat162*)&hp.x = __halves2bfloat162(h0, h1);
        *(__nv_bfloat162*)&hp.y = __halves2bfloat162(h2, h3);
        *(__nv_bfloat162*)&lp.x = __halves2bfloat162(l0, l1);
        *(__nv_bfloat162*)&lp.y = __halves2bfloat162(l2, l3);
        __nv_bfloat16* qb = qs + ((size_t)bh * SEQ + t) * DKS + d4 * 4;
        *(uint2*)(qb)       = hp;
        *(uint2*)(qb + DK)  = hp;
        *(uint2*)(qb + 2 * DK) = lp;
    }
    // K: B-style [hi|lo|hi]
    {
        __nv_bfloat16 h0,h1,h2,h3,l0,l1,l2,l3;
        split_bf16(kv.x, h0, l0); split_bf16(kv.y, h1, l1);
        split_bf16(kv.z, h2, l2); split_bf16(kv.w, h3, l3);
        uint2 hp, lp;
        *(__nv_bfloat162*)&hp.x = __halves2bfloat162(h0, h1);
        *(__nv_bfloat162*)&hp.y = __halves2bfloat162(h2, h3);
        *(__nv_bfloat162*)&lp.x = __halves2bfloat162(l0, l1);
        *(__nv_bfloat162*)&lp.y = __halves2bfloat162(l2, l3);
        __nv_bfloat16* kb = ks + ((size_t)bh * SEQ + t) * DKS + d4 * 4;
        *(uint2*)(kb)       = hp;
        *(uint2*)(kb + DK)  = lp;
        *(uint2*)(kb + 2 * DK) = hp;
    }
    // V^T: B-style over s-dim: row d, cols [hi@t | lo@1024+t | hi@2048+t]
    {
        float vs[4] = {vv.x, vv.y, vv.z, vv.w};
#pragma unroll
        for (int j = 0; j < 4; j++) {
            __nv_bfloat16 hi, lo;
            split_bf16(vs[j], hi, lo);
            __nv_bfloat16* vb = vt + ((size_t)bh * DK + d4 * 4 + j) * SS;
            vb[t] = hi; vb[SEQ + t] = lo; vb[2 * SEQ + t] = hi;
        }
    }
}

// ---------------------------------------------------------------------------
// mma.sync common pieces
// ---------------------------------------------------------------------------
#define STAGE_BYTES 32768
#define GEMM_DSMEM  (2 * STAGE_BYTES)
#define PV_STAGE    24576
#define PV_DSMEM    (2 * PV_STAGE)

__device__ __forceinline__ uint32_t smem_u32(const void* p) {
    uint32_t a;
    asm("{ .reg .u64 t; cvta.to.shared.u64 t, %1; cvt.u32.u64 %0, t; }" : "=r"(a) : "l"(p));
    return a;
}

#define CP_ASYNC16(dst, src) \
    asm volatile("cp.async.cg.shared.global [%0], [%1], 16;" :: "r"(dst), "l"(src) : "memory")
#define CP_COMMIT() asm volatile("cp.async.commit_group;" ::: "memory")
#define CP_WAIT1()  asm volatile("cp.async.wait_group 1;" ::: "memory")

#define LDMATRIX_X4(r0, r1, r2, r3, addr) \
    asm volatile("ldmatrix.sync.aligned.m8n8.x4.shared.b16 {%0,%1,%2,%3}, [%4];" \
        : "=r"(r0), "=r"(r1), "=r"(r2), "=r"(r3) : "r"(addr))

__device__ __forceinline__ void mma16816(float* d, const uint32_t* a, const uint32_t* b) {
    asm volatile(
        "mma.sync.aligned.m16n8k16.row.col.f32.bf16.bf16.f32 "
        "{%0,%1,%2,%3}, {%4,%5,%6,%7}, {%8,%9}, {%0,%1,%2,%3};"
        : "+f"(d[0]), "+f"(d[1]), "+f"(d[2]), "+f"(d[3])
        : "r"(a[0]), "r"(a[1]), "r"(a[2]), "r"(a[3]), "r"(b[0]), "r"(b[1]));
}

// ---------------------------------------------------------------------------
// Linear GEMM: C[M,N] = A[M,Kp] @ B[N,Kp]^T (+bias, +opt residual / relu+split)
// 128x128 CTA tile, 256 threads (8 warps 4x2), K-chunk 64, 2-stage cp.async.
// EP: 0 = fp32 out, 1 = fp32 + residual, 2 = relu + split-bf16 out (A-style)
// ---------------------------------------------------------------------------
template<int EP>
__global__ __launch_bounds__(256) void mma_gemm(
    const __nv_bfloat16* __restrict__ A, const __nv_bfloat16* __restrict__ B,
    const float* __restrict__ bias, const float* __restrict__ res,
    float* __restrict__ Cf, __nv_bfloat16* __restrict__ Cb,
    int N, int Kp)
{
    extern __shared__ __align__(16) char dsm[];
    const uint32_t sbase = smem_u32(dsm);

    const int tid  = threadIdx.x;
    const int wid  = tid >> 5;
    const int lane = tid & 31;
    const int g    = lane >> 2;
    const int cq   = lane & 3;
    const int lr   = lane & 15;
    const int lc   = lane >> 4;
    const int wm   = wid & 3;
    const int wn   = wid >> 2;
    const int n0   = blockIdx.x * 128;
    const int m0   = blockIdx.y * 128;

    const __nv_bfloat16* Ap = A + (size_t)m0 * Kp;
    const __nv_bfloat16* Bp = B + (size_t)n0 * Kp;
    const int nchunk = Kp >> 6;

    float acc[2][8][4];
#pragma unroll
    for (int mi = 0; mi < 2; mi++)
#pragma unroll
        for (int ni = 0; ni < 8; ni++)
#pragma unroll
            for (int r = 0; r < 4; r++) acc[mi][ni][r] = 0.0f;

    auto load_stage = [&](int c, int stage) {
        const int k0 = c << 6;
        const uint32_t sA = sbase + stage * STAGE_BYTES;
        const uint32_t sB = sA + 16384;
#pragma unroll
        for (int i = 0; i < 4; i++) {
            int lin = tid + i * 256;
            int r   = lin >> 3;
            int c16 = lin & 7;
            uint32_t off = (uint32_t)(r * 128 + ((c16 ^ (r & 7)) * 16));
            CP_ASYNC16(sA + off, (const void*)(Ap + (size_t)r * Kp + k0 + c16 * 8));
            CP_ASYNC16(sB + off, (const void*)(Bp + (size_t)r * Kp + k0 + c16 * 8));
        }
    };

    load_stage(0, 0);
    CP_COMMIT();

    for (int c = 0; c < nchunk; c++) {
        const int cur = c & 1;
        if (c + 1 < nchunk) load_stage(c + 1, cur ^ 1);
        CP_COMMIT();
        CP_WAIT1();
        __syncthreads();

        const uint32_t sA = sbase + cur * STAGE_BYTES;
        const uint32_t sB = sA + 16384;

#pragma unroll
        for (int ks = 0; ks < 4; ks++) {
            const int kblk = ks * 2 + lc;
            uint32_t afr[2][4], bfr[4][4];
#pragma unroll
            for (int mi = 0; mi < 2; mi++) {
                int row = wm * 32 + mi * 16 + lr;
                uint32_t addr = sA + (uint32_t)(row * 128 + ((kblk ^ (row & 7)) * 16));
                LDMATRIX_X4(afr[mi][0], afr[mi][1], afr[mi][2], afr[mi][3], addr);
            }
#pragma unroll
            for (int p = 0; p < 4; p++) {
                int row = wn * 64 + p * 16 + lr;
                uint32_t addr = sB + (uint32_t)(row * 128 + ((kblk ^ (row & 7)) * 16));
                LDMATRIX_X4(bfr[p][0], bfr[p][1], bfr[p][2], bfr[p][3], addr);
            }
#pragma unroll
            for (int mi = 0; mi < 2; mi++)
#pragma unroll
                for (int ni = 0; ni < 8; ni++) {
                    const int p = ni >> 1, o = ni & 1;
                    uint32_t b2[2] = { bfr[p][o], bfr[p][2 + o] };
                    mma16816(acc[mi][ni], afr[mi], b2);
                }
        }
        __syncthreads();
    }

#pragma unroll
    for (int mi = 0; mi < 2; mi++) {
#pragma unroll
        for (int half = 0; half < 2; half++) {
            const int m = m0 + wm * 32 + mi * 16 + g + half * 8;
#pragma unroll
            for (int ni = 0; ni < 8; ni++) {
                const int n = n0 + wn * 64 + ni * 8 + 2 * cq;
                float2 bv = *(const float2*)(bias + n);
                float v0 = acc[mi][ni][half * 2 + 0] + bv.x;
                float v1 = acc[mi][ni][half * 2 + 1] + bv.y;
                if (EP == 2) {
                    v0 = fmaxf(v0, 0.f); v1 = fmaxf(v1, 0.f);
                    __nv_bfloat16 h0, h1, l0, l1;
                    split_bf16(v0, h0, l0); split_bf16(v1, h1, l1);
                    uint32_t hp, lp;
                    *(__nv_bfloat162*)&hp = __halves2bfloat162(h0, h1);
                    *(__nv_bfloat162*)&lp = __halves2bfloat162(l0, l1);
                    size_t rb = (size_t)m * 3 * N;
                    *(uint32_t*)(Cb + rb + n)         = hp;
                    *(uint32_t*)(Cb + rb + N + n)     = hp;
                    *(uint32_t*)(Cb + rb + 2 * N + n) = lp;
                } else {
                    if (EP == 1) {
                        float2 rv = *(const float2*)(res + (size_t)m * N + n);
                        v0 += rv.x; v1 += rv.y;
                    }
                    *(float2*)(Cf + (size_t)m * N + n) = make_float2(v0, v1);
                }
            }
        }
    }
}

// ---------------------------------------------------------------------------
// Batched score GEMM: S[bh] = Qs[bh] @ Ks[bh]^T   (M=N=1024, Kp=192)
// Same datapath as mma_gemm; grid (8, 8, 64).
// ---------------------------------------------------------------------------
__global__ __launch_bounds__(256) void score_gemm(
    const __nv_bfloat16* __restrict__ Qs, const __nv_bfloat16* __restrict__ Ks,
    float* __restrict__ S)
{
    extern __shared__ __align__(16) char dsm[];
    const uint32_t sbase = smem_u32(dsm);

    const int tid  = threadIdx.x;
    const int wid  = tid >> 5;
    const int lane = tid & 31;
    const int g    = lane >> 2;
    const int cq   = lane & 3;
    const int lr   = lane & 15;
    const int lc   = lane >> 4;
    const int wm   = wid & 3;
    const int wn   = wid >> 2;
    const int n0   = blockIdx.x * 128;
    const int m0   = blockIdx.y * 128;
    const int bh   = blockIdx.z;
    const int Kp   = DKS;

    const __nv_bfloat16* Ap = Qs + (size_t)bh * SEQ * DKS + (size_t)m0 * Kp;
    const __nv_bfloat16* Bp = Ks + (size_t)bh * SEQ * DKS + (size_t)n0 * Kp;
    float* Sp = S + (size_t)bh * SEQ * SEQ;

    float acc[2][8][4];
#pragma unroll
    for (int mi = 0; mi < 2; mi++)
#pragma unroll
        for (int ni = 0; ni < 8; ni++)
#pragma unroll
            for (int r = 0; r < 4; r++) acc[mi][ni][r] = 0.0f;

    auto load_stage = [&](int c, int stage) {
        const int k0 = c << 6;
        const uint32_t sA = sbase + stage * STAGE_BYTES;
        const uint32_t sB = sA + 16384;
#pragma unroll
        for (int i = 0; i < 4; i++) {
            int lin = tid + i * 256;
            int r   = lin >> 3;
            int c16 = lin & 7;
            uint32_t off = (uint32_t)(r * 128 + ((c16 ^ (r & 7)) * 16));
            CP_ASYNC16(sA + off, (const void*)(Ap + (size_t)r * Kp + k0 + c16 * 8));
            CP_ASYNC16(sB + off, (const void*)(Bp + (size_t)r * Kp + k0 + c16 * 8));
        }
    };

    load_stage(0, 0);
    CP_COMMIT();

    for (int c = 0; c < 3; c++) {
        const int cur = c & 1;
        if (c + 1 < 3) load_stage(c + 1, cur ^ 1);
        CP_COMMIT();
        CP_WAIT1();
        __syncthreads();

        const uint32_t sA = sbase + cur * STAGE_BYTES;
        const uint32_t sB = sA + 16384;

#pragma unroll
        for (int ks = 0; ks < 4; ks++) {
            const int kblk = ks * 2 + lc;
            uint32_t afr[2][4], bfr[4][4];
#pragma unroll
            for (int mi = 0; mi < 2; mi++) {
                int row = wm * 32 + mi * 16 + lr;
                uint32_t addr = sA + (uint32_t)(row * 128 + ((kblk ^ (row & 7)) * 16));
                LDMATRIX_X4(afr[mi][0], afr[mi][1], afr[mi][2], afr[mi][3], addr);
            }
#pragma unroll
            for (int p = 0; p < 4; p++) {
                int row = wn * 64 + p * 16 + lr;
                uint32_t addr = sB + (uint32_t)(row * 128 + ((kblk ^ (row & 7)) * 16));
                LDMATRIX_X4(bfr[p][0], bfr[p][1], bfr[p][2], bfr[p][3], addr);
            }
#pragma unroll
            for (int mi = 0; mi < 2; mi++)
#pragma unroll
                for (int ni = 0; ni < 8; ni++) {
                    const int p = ni >> 1, o = ni & 1;
                    uint32_t b2[2] = { bfr[p][o], bfr[p][2 + o] };
                    mma16816(acc[mi][ni], afr[mi], b2);
                }
        }
        __syncthreads();
    }

#pragma unroll
    for (int mi = 0; mi < 2; mi++)
#pragma unroll
        for (int half = 0; half < 2; half++) {
            const int m = m0 + wm * 32 + mi * 16 + g + half * 8;
#pragma unroll
            for (int ni = 0; ni < 8; ni++) {
                const int n = n0 + wn * 64 + ni * 8 + 2 * cq;
                *(float2*)(Sp + (size_t)m * SEQ + n) =
                    make_float2(acc[mi][ni][half * 2], acc[mi][ni][half * 2 + 1]);
            }
        }
}

// ---------------------------------------------------------------------------
// Softmax over score rows; writes normalized P as split [hi|hi|lo] (width 3072)
// one block per row (bh*1024 + t), 128 threads x 8 cols.
// ---------------------------------------------------------------------------
__global__ __launch_bounds__(128) void softmax_kernel(
    const float* __restrict__ S, __nv_bfloat16* __restrict__ P)
{
    __shared__ float red[4];
    const int row = blockIdx.x;
    const int tid = threadIdx.x;
    const float* sr = S + (size_t)row * SEQ;

    float4 a = *(const float4*)(sr + tid * 8);
    float4 b = *(const float4*)(sr + tid * 8 + 4);
    float m = fmaxf(fmaxf(fmaxf(a.x, a.y), fmaxf(a.z, a.w)),
                    fmaxf(fmaxf(b.x, b.y), fmaxf(b.z, b.w)));
#pragma unroll
    for (int o = 16; o > 0; o >>= 1) m = fmaxf(m, __shfl_xor_sync(0xffffffffu, m, o));
    if ((tid & 31) == 0) red[tid >> 5] = m;
    __syncthreads();
    m = fmaxf(fmaxf(red[0], red[1]), fmaxf(red[2], red[3]));
    __syncthreads();

    float p[8];
    p[0] = __expf(a.x - m); p[1] = __expf(a.y - m);
    p[2] = __expf(a.z - m); p[3] = __expf(a.w - m);
    p[4] = __expf(b.x - m); p[5] = __expf(b.y - m);
    p[6] = __expf(b.z - m); p[7] = __expf(b.w - m);
    float s = p[0] + p[1] + p[2] + p[3] + p[4] + p[5] + p[6] + p[7];
#pragma unroll
    for (int o = 16; o > 0; o >>= 1) s += __shfl_xor_sync(0xffffffffu, s, o);
    if ((tid & 31) == 0) red[tid >> 5] = s;
    __syncthreads();
    float inv = 1.0f / (red[0] + red[1] + red[2] + red[3]);

    __nv_bfloat16 hi[8], lo[8];
#pragma unroll
    for (int i = 0; i < 8; i++) split_bf16(p[i] * inv, hi[i], lo[i]);
    uint4 hp, lp;
    *(__nv_bfloat162*)&hp.x = __halves2bfloat162(hi[0], hi[1]);
    *(__nv_bfloat162*)&hp.y = __halves2bfloat162(hi[2], hi[3]);
    *(__nv_bfloat162*)&hp.z = __halves2bfloat162(hi[4], hi[5]);
    *(__nv_bfloat162*)&hp.w = __halves2bfloat162(hi[6], hi[7]);
    *(__nv_bfloat162*)&lp.x = __halves2bfloat162(lo[0], lo[1]);
    *(__nv_bfloat162*)&lp.y = __halves2bfloat162(lo[2], lo[3]);
    *(__nv_bfloat162*)&lp.z = __halves2bfloat162(lo[4], lo[5]);
    *(__nv_bfloat162*)&lp.w = __halves2bfloat162(lo[6], lo[7]);

    __nv_bfloat16* pr = P + (size_t)row * SS + tid * 8;
    *(uint4*)(pr)           = hp;
    *(uint4*)(pr + SEQ)     = hp;
    *(uint4*)(pr + 2 * SEQ) = lp;
}

// ---------------------------------------------------------------------------
// Batched PV GEMM: ctx[bh] = P[bh] @ Vt[bh]^T  (M=1024, N=64, Kp=3072)
// CTA tile 128x64, 8 warps x (16 rows x 64 cols). Writes ctx split into g_ccvt.
// grid (1, 8, 64).
// ---------------------------------------------------------------------------
__global__ __launch_bounds__(256) void pv_gemm(
    const __nv_bfloat16* __restrict__ P, const __nv_bfloat16* __restrict__ Vt,
    __nv_bfloat16* __restrict__ Ccvt)
{
    extern __shared__ __align__(16) char dsm[];
    const uint32_t sbase = smem_u32(dsm);

    const int tid  = threadIdx.x;
    const int wid  = tid >> 5;     // 0..7 -> 16 rows each
    const int lane = tid & 31;
    const int g    = lane >> 2;
    const int cq   = lane & 3;
    const int lr   = lane & 15;
    const int lc   = lane >> 4;
    const int m0   = blockIdx.y * 128;
    const int bh   = blockIdx.z;

    const __nv_bfloat16* Ap = P  + (size_t)bh * SEQ * SS + (size_t)m0 * SS;
    const __nv_bfloat16* Bp = Vt + (size_t)bh * DK * SS;

    float acc[8][4];
#pragma unroll
    for (int ni = 0; ni < 8; ni++)
#pragma unroll
        for (int r = 0; r < 4; r++) acc[ni][r] = 0.0f;

    auto load_stage = [&](int c, int stage) {
        const int k0 = c << 6;
        const uint32_t sA = sbase + stage * PV_STAGE;
        const uint32_t sB = sA + 16384;
#pragma unroll
        for (int i = 0; i < 4; i++) {
            int lin = tid + i * 256;
            int r   = lin >> 3;
            int c16 = lin & 7;
            uint32_t off = (uint32_t)(r * 128 + ((c16 ^ (r & 7)) * 16));
            CP_ASYNC16(sA + off, (const void*)(Ap + (size_t)r * SS + k0 + c16 * 8));
        }
#pragma unroll
        for (int i = 0; i < 2; i++) {
            int lin = tid + i * 256;
            int r   = lin >> 3;           // 0..63
            int c16 = lin & 7;
            uint32_t off = (uint32_t)(r * 128 + ((c16 ^ (r & 7)) * 16));
            CP_ASYNC16(sB + off, (const void*)(Bp + (size_t)r * SS + k0 + c16 * 8));
        }
    };

    load_stage(0, 0);
    CP_COMMIT();

    const int nchunk = SS >> 6;   // 48
    for (int c = 0; c < nchunk; c++) {
        const int cur = c & 1;
        if (c + 1 < nchunk) load_stage(c + 1, cur ^ 1);
        CP_COMMIT();
        CP_WAIT1();
        __syncthreads();

        const uint32_t sA = sbase + cur * PV_STAGE;
        const uint32_t sB = sA + 16384;

#pragma unroll
        for (int ks = 0; ks < 4; ks++) {
            const int kblk = ks * 2 + lc;
            uint32_t afr[4], bfr[4][4];
            {
                int row = wid * 16 + lr;
                uint32_t addr = sA + (uint32_t)(row * 128 + ((kblk ^ (row & 7)) * 16));
                LDMATRIX_X4(afr[0], afr[1], afr[2], afr[3], addr);
            }
#pragma unroll
            for (int p = 0; p < 4; p++) {
                int row = p * 16 + lr;
                uint32_t addr = sB + (uint32_t)(row * 128 + ((kblk ^ (row & 7)) * 16));
                LDMATRIX_X4(bfr[p][0], bfr[p][1], bfr[p][2], bfr[p][3], addr);
            }
#pragma unroll
            for (int ni = 0; ni < 8; ni++) {
                const int p = ni >> 1, o = ni & 1;
                uint32_t b2[2] = { bfr[p][o], bfr[p][2 + o] };
                mma16816(acc[ni], afr, b2);
            }
        }
        __syncthreads();
    }

    // epilogue: ctx(m, n) -> split write into g_ccvt [tok][3*512] at col h*64+n
    const int b = bh >> 3, h = bh & 7;
#pragma unroll
    for (int half = 0; half < 2; half++) {
        const int m = m0 + wid * 16 + g + half * 8;
        const size_t tok = (size_t)b * SEQ + m;
        const size_t rb = tok * (3 * NU);
#pragma unroll
        for (int ni = 0; ni < 8; ni++) {
            const int col = h * DK + ni * 8 + 2 * cq;
            float v0 = acc[ni][half * 2 + 0];
            float v1 = acc[ni][half * 2 + 1];
            __nv_bfloat16 h0, h1, l0, l1;
            split_bf16(v0, h0, l0); split_bf16(v1, h1, l1);
            uint32_t hp, lp;
            *(__nv_bfloat162*)&hp = __halves2bfloat162(h0, h1);
            *(__nv_bfloat162*)&lp = __halves2bfloat162(l0, l1);
            *(uint32_t*)(Ccvt + rb + col)          = hp;
            *(uint32_t*)(Ccvt + rb + NU + col)     = hp;
            *(uint32_t*)(Ccvt + rb + 2 * NU + col) = lp;
        }
    }
}

// ---------------------------------------------------------------------------
// LayerNorm over rows of 512; optionally also writes split-bf16 (A-style)
// ---------------------------------------------------------------------------
template<bool CVT>
__global__ __launch_bounds__(128) void ln_kernel(
    const float* __restrict__ X, const float* __restrict__ gamma,
    const float* __restrict__ beta, float* __restrict__ O,
    __nv_bfloat16* __restrict__ Ocvt)
{
    __shared__ float red[4];
    const int row = blockIdx.x;
    const int tid = threadIdx.x;

    float4 v = *(const float4*)(X + (size_t)row * NU + tid * 4);
    float s = v.x + v.y + v.z + v.w;
#pragma unroll
    for (int o = 16; o > 0; o >>= 1) s += __shfl_xor_sync(0xffffffffu, s, o);
    if ((tid & 31) == 0) red[tid >> 5] = s;
    __syncthreads();
    float mean = (red[0] + red[1] + red[2] + red[3]) * (1.0f / 512.0f);
    __syncthreads();

    float dx = v.x - mean, dy = v.y - mean, dz = v.z - mean, dw = v.w - mean;
    float sq = dx * dx + dy * dy + dz * dz + dw * dw;
#pragma unroll
    for (int o = 16; o > 0; o >>= 1) sq += __shfl_xor_sync(0xffffffffu, sq, o);
    if ((tid & 31) == 0) red[tid >> 5] = sq;
    __syncthreads();
    float var = (red[0] + red[1] + red[2] + red[3]) * (1.0f / 512.0f);
    float inv = rsqrtf(var + 1e-5f);

    float4 g = *(const float4*)(gamma + tid * 4);
    float4 b = *(const float4*)(beta  + tid * 4);
    float4 o4;
    o4.x = dx * inv * g.x + b.x;
    o4.y = dy * inv * g.y + b.y;
    o4.z = dz * inv * g.z + b.z;
    o4.w = dw * inv * g.w + b.w;
    *(float4*)(O + (size_t)row * NU + tid * 4) = o4;

    if (CVT) {
        __nv_bfloat16 h0, h1, h2, h3, l0, l1, l2, l3;
        split_bf16(o4.x, h0, l0); split_bf16(o4.y, h1, l1);
        split_bf16(o4.z, h2, l2); split_bf16(o4.w, h3, l3);
        uint2 hp, lp;
        *(__nv_bfloat162*)&hp.x = __halves2bfloat162(h0, h1);
        *(__nv_bfloat162*)&hp.y = __halves2bfloat162(h2, h3);
        *(__nv_bfloat162*)&lp.x = __halves2bfloat162(l0, l1);
        *(__nv_bfloat162*)&lp.y = __halves2bfloat162(l2, l3);
        size_t rb = (size_t)row * (3 * NU);
        int col = tid * 4;
        *(uint2*)(Ocvt + rb + col)            = hp;
        *(uint2*)(Ocvt + rb + NU + col)       = hp;
        *(uint2*)(Ocvt + rb + 2 * NU + col)   = lp;
    }
}

// ---------------------------------------------------------------------------
// Host orchestration (graph-capturable: kernel launches only)
// ---------------------------------------------------------------------------
extern "C" void kernel_launch(void* const* d_in, const int* in_sizes, int n_in,
                              void* d_out, int out_size)
{
    (void)in_sizes; (void)n_in; (void)out_size;

    const float* x     = (const float*)d_in[0];
    const float* Win   = (const float*)d_in[1];
    const float* bin   = (const float*)d_in[2];
    const float* ln1_g = (const float*)d_in[3];
    const float* ln1_b = (const float*)d_in[4];
    const float* Wq    = (const float*)d_in[5];
    const float* bq    = (const float*)d_in[6];
    const float* Wk    = (const float*)d_in[7];
    const float* bk    = (const float*)d_in[8];
    const float* Wv    = (const float*)d_in[9];
    const float* bv    = (const float*)d_in[10];
    const float* Wo    = (const float*)d_in[11];
    const float* bo    = (const float*)d_in[12];
    const float* ln2_g = (const float*)d_in[13];
    const float* ln2_b = (const float*)d_in[14];
    const float* W1    = (const float*)d_in[15];
    const float* b1    = (const float*)d_in[16];
    const float* W2    = (const float*)d_in[17];
    const float* b2    = (const float*)d_in[18];
    const float* lno_g = (const float*)d_in[19];
    const float* lno_b = (const float*)d_in[20];
    float* out = (float*)d_out;

    float *e, *qkv, *bqkv, *sc;
    __nv_bfloat16 *xc, *ec, *cc, *hc, *Winc, *Wqkvc, *Woc, *W1c, *W2c;
    __nv_bfloat16 *qs, *ks, *vt, *ps;
    cudaGetSymbolAddress((void**)&e,    g_e);
    cudaGetSymbolAddress((void**)&qkv,  g_qkv);
    cudaGetSymbolAddress((void**)&bqkv, g_bqkv);
    cudaGetSymbolAddress((void**)&sc,   g_sc);
    cudaGetSymbolAddress((void**)&xc,   g_xcvt);
    cudaGetSymbolAddress((void**)&ec,   g_ecvt);
    cudaGetSymbolAddress((void**)&cc,   g_ccvt);
    cudaGetSymbolAddress((void**)&hc,   g_hcvt);
    cudaGetSymbolAddress((void**)&Winc,  g_Winc);
    cudaGetSymbolAddress((void**)&Wqkvc, g_Wqkvc);
    cudaGetSymbolAddress((void**)&Woc,   g_Woc);
    cudaGetSymbolAddress((void**)&W1c,   g_W1c);
    cudaGetSymbolAddress((void**)&W2c,   g_W2c);
    cudaGetSymbolAddress((void**)&qs,   g_qs);
    cudaGetSymbolAddress((void**)&ks,   g_ks);
    cudaGetSymbolAddress((void**)&vt,   g_vt);
    cudaGetSymbolAddress((void**)&ps,   g_ps);

    cudaFuncSetAttribute(mma_gemm<0>, cudaFuncAttributeMaxDynamicSharedMemorySize, GEMM_DSMEM);
    cudaFuncSetAttribute(mma_gemm<1>, cudaFuncAttributeMaxDynamicSharedMemorySize, GEMM_DSMEM);
    cudaFuncSetAttribute(mma_gemm<2>, cudaFuncAttributeMaxDynamicSharedMemorySize, GEMM_DSMEM);
    cudaFuncSetAttribute(score_gemm,  cudaFuncAttributeMaxDynamicSharedMemorySize, GEMM_DSMEM);
    cudaFuncSetAttribute(pv_gemm,     cudaFuncAttributeMaxDynamicSharedMemorySize, PV_DSMEM);

    // operand conversions (every launch; deterministic)
    {
        int t;
        t = NU * IDIM;          convert_B_kernel<<<(t + 255) / 256, 256>>>(Win, Winc, IDIM, t);
        for (int i = 0; i < NLAYERS; i++) {
            const size_t lb = (size_t)i * QKVW * 3 * NU;
            int tt = NU * NU;
            convert_B_kernel<<<(tt + 255) / 256, 256>>>(Wq + (size_t)i * NU * NU, Wqkvc + lb, NU, tt);
            convert_B_kernel<<<(tt + 255) / 256, 256>>>(Wk + (size_t)i * NU * NU, Wqkvc + lb + (size_t)NU * 3 * NU, NU, tt);
            convert_B_kernel<<<(tt + 255) / 256, 256>>>(Wv + (size_t)i * NU * NU, Wqkvc + lb + (size_t)2 * NU * 3 * NU, NU, tt);
        }
        t = NLAYERS * NU * NU;  convert_B_kernel<<<(t + 255) / 256, 256>>>(Wo, Woc, NU, t);
        t = NLAYERS * EU * NU;  convert_B_kernel<<<(t + 255) / 256, 256>>>(W1, W1c, NU, t);
        t = NLAYERS * NU * EU;  convert_B_kernel<<<(t + 255) / 256, 256>>>(W2, W2c, EU, t);
        t = TOK * IDIM;         convert_A_kernel<<<(t + 255) / 256, 256>>>(x, xc, IDIM, t);
        t = NLAYERS * QKVW;     pack_bqkv_kernel<<<(t + 255) / 256, 256>>>(bq, bk, bv, bqkv);
    }

    dim3 g512 (NU   / 128, TOK / 128);   // (4, 64)
    dim3 gqkv (QKVW / 128, TOK / 128);   // (12, 64)
    dim3 g2048(EU   / 128, TOK / 128);   // (16, 64)
    dim3 gscore(SEQ / 128, SEQ / 128, BH);   // (8, 8, 64)
    dim3 gpv(1, SEQ / 128, BH);              // (1, 8, 64)
    const int cvattn_blocks = (BH * SEQ * 16 + 255) / 256;

    // input projection: e = x @ Win^T + bin
    mma_gemm<0><<<g512, 256, GEMM_DSMEM>>>(xc, Winc, bin, nullptr, e, nullptr, NU, 3 * IDIM);

    for (int i = 0; i < NLAYERS; i++) {
        const size_t wqkv = (size_t)i * QKVW * 3 * NU;
        const size_t wo   = (size_t)i * NU * 3 * NU;
        const size_t w1o  = (size_t)i * EU * 3 * NU;
        const size_t w2o  = (size_t)i * NU * 3 * EU;

        ln_kernel<true><<<TOK, 128>>>(e, ln1_g + i * NU, ln1_b + i * NU, e, ec);

        // fused qkv = ln(e) @ [Wq|Wk|Wv]^T + [bq|bk|bv]
        mma_gemm<0><<<gqkv, 256, GEMM_DSMEM>>>(ec, Wqkvc + wqkv, bqkv + i * QKVW, nullptr,
                                               qkv, nullptr, QKVW, 3 * NU);

        // tensorized attention pipeline
        convert_attn_kernel<<<cvattn_blocks, 256>>>(qkv, qs, ks, vt);
        score_gemm<<<gscore, 256, GEMM_DSMEM>>>(qs, ks, sc);
        softmax_kernel<<<BH * SEQ, 128>>>(sc, ps);
        pv_gemm<<<gpv, 256, PV_DSMEM>>>(ps, vt, cc);

        // e = e + ctx @ Wo^T + bo
        mma_gemm<1><<<g512, 256, GEMM_DSMEM>>>(cc, Woc + wo, bo + i * NU, e, e, nullptr, NU, 3 * NU);

        ln_kernel<true><<<TOK, 128>>>(e, ln2_g + i * NU, ln2_b + i * NU, e, ec);

        // h = relu(e @ W1^T + b1) -> split bf16
        mma_gemm<2><<<g2048, 256, GEMM_DSMEM>>>(ec, W1c + w1o, b1 + (size_t)i * EU, nullptr,
                                                nullptr, hc, EU, 3 * NU);
        // e = e + h @ W2^T + b2
        mma_gemm<1><<<g512, 256, GEMM_DSMEM>>>(hc, W2c + w2o, b2 + i * NU, e, e, nullptr, NU, 3 * EU);
    }

    ln_kernel<false><<<TOK, 128>>>(e, lno_g, lno_b, out, nullptr);
}

// round 11
// speedup vs baseline: 3.5803x; 1.2030x over previous
#include <cuda_runtime.h>
#include <cuda_bf16.h>
#include <math.h>
#include <stdint.h>

// ---------------------------------------------------------------------------
// Problem constants
// ---------------------------------------------------------------------------
#define TOK      8192
#define IDIM     256
#define NU       512
#define EU       2048
#define NLAYERS  4
#define HEADS    8
#define DK       64
#define SEQ      1024
#define NBATCH   8
#define QKVW     1536
#define BH       (NBATCH * HEADS)   // 64

// ---------------------------------------------------------------------------
// Scratch (static device memory; allocation APIs are forbidden)
// ---------------------------------------------------------------------------
__device__ float g_e  [TOK * NU];
__device__ float g_qkv[TOK * QKVW];

// split-bf16 operand buffers (K-concat: activations [hi|hi|lo], weights [hi|lo|hi])
__device__ __nv_bfloat16 g_xcvt [TOK * 3 * IDIM];
__device__ __nv_bfloat16 g_ecvt [TOK * 3 * NU];
__device__ __nv_bfloat16 g_ccvt [TOK * 3 * NU];
__device__ __nv_bfloat16 g_hcvt [TOK * 3 * EU];

__device__ __nv_bfloat16 g_Winc  [NU * 3 * IDIM];
__device__ __nv_bfloat16 g_Wqkvc [NLAYERS * QKVW * 3 * NU];
__device__ __nv_bfloat16 g_Woc   [NLAYERS * NU * 3 * NU];
__device__ __nv_bfloat16 g_W1c   [NLAYERS * EU * 3 * NU];
__device__ __nv_bfloat16 g_W2c   [NLAYERS * NU * 3 * EU];
__device__ float         g_bqkv  [NLAYERS * QKVW];

// attention operands, 2-slab [hi|lo] layouts
__device__ __nv_bfloat16 g_qs [BH * SEQ * 128];        // [bh][t][hi64|lo64] (scaled)
__device__ __nv_bfloat16 g_ks [BH * SEQ * 128];        // [bh][t][hi64|lo64]
__device__ __nv_bfloat16 g_vt [BH * DK * 2 * SEQ];     // [bh][d][hi@s | lo@1024+s]

// ---------------------------------------------------------------------------
// split helpers
// ---------------------------------------------------------------------------
__device__ __forceinline__ void split_bf16(float f, __nv_bfloat16& hi, __nv_bfloat16& lo) {
    hi = __float2bfloat16(f);
    lo = __float2bfloat16(f - __bfloat162float(hi));
}
__device__ __forceinline__ uint32_t packbf(float a, float b) {
    __nv_bfloat162 t = __halves2bfloat162(__float2bfloat16(a), __float2bfloat16(b));
    return *(uint32_t*)&t;
}
__device__ __forceinline__ float lof(float a) {
    return a - __bfloat162float(__float2bfloat16(a));
}

// weights: out row = [hi | lo | hi], row width 3K
__global__ void convert_B_kernel(const float* __restrict__ W, __nv_bfloat16* __restrict__ out,
                                 int K, int total) {
    int idx = blockIdx.x * 256 + threadIdx.x;
    if (idx >= total) return;
    int n = idx / K, k = idx - n * K;
    __nv_bfloat16 hi, lo;
    split_bf16(W[idx], hi, lo);
    size_t base = (size_t)n * 3 * K;
    out[base + k] = hi;
    out[base + K + k] = lo;
    out[base + 2 * K + k] = hi;
}

// activations: out row = [hi | hi | lo]
__global__ void convert_A_kernel(const float* __restrict__ A, __nv_bfloat16* __restrict__ out,
                                 int K, int total) {
    int idx = blockIdx.x * 256 + threadIdx.x;
    if (idx >= total) return;
    int n = idx / K, k = idx - n * K;
    __nv_bfloat16 hi, lo;
    split_bf16(A[idx], hi, lo);
    size_t base = (size_t)n * 3 * K;
    out[base + k] = hi;
    out[base + K + k] = hi;
    out[base + 2 * K + k] = lo;
}

// pack per-layer q|k|v biases into 1536-wide rows
__global__ void pack_bqkv_kernel(const float* __restrict__ bq, const float* __restrict__ bk,
                                 const float* __restrict__ bv, float* __restrict__ out) {
    int i = blockIdx.x * 256 + threadIdx.x;
    if (i >= NLAYERS * QKVW) return;
    int l = i / QKVW, c = i - l * QKVW;
    float v = (c < NU) ? bq[l * NU + c]
            : (c < 2 * NU) ? bk[l * NU + c - NU]
            : bv[l * NU + c - 2 * NU];
    out[i] = v;
}

// slice fused qkv into per-head [hi|lo] operands; Q has 1/8 scale folded in
__global__ void convert_attn_kernel(const float* __restrict__ QKV,
    __nv_bfloat16* __restrict__ qs, __nv_bfloat16* __restrict__ ks,
    __nv_bfloat16* __restrict__ vt)
{
    int idx = blockIdx.x * 256 + threadIdx.x;
    if (idx >= BH * SEQ * 16) return;
    int d4 = idx & 15;
    int t  = (idx >> 4) & (SEQ - 1);
    int bh = idx >> 14;
    int b = bh >> 3, h = bh & 7;
    const float* row = QKV + (size_t)(b * SEQ + t) * QKVW + h * DK + d4 * 4;
    float4 qv = *(const float4*)(row);
    float4 kv = *(const float4*)(row + NU);
    float4 vv = *(const float4*)(row + 2 * NU);

    {   // Q (scaled)
        __nv_bfloat16 h0,h1,h2,h3,l0,l1,l2,l3;
        split_bf16(qv.x * 0.125f, h0, l0); split_bf16(qv.y * 0.125f, h1, l1);
        split_bf16(qv.z * 0.125f, h2, l2); split_bf16(qv.w * 0.125f, h3, l3);
        uint2 hp, lp;
        *(__nv_bfloat162*)&hp.x = __halves2bfloat162(h0, h1);
        *(__nv_bfloat162*)&hp.y = __halves2bfloat162(h2, h3);
        *(__nv_bfloat162*)&lp.x = __halves2bfloat162(l0, l1);
        *(__nv_bfloat162*)&lp.y = __halves2bfloat162(l2, l3);
        __nv_bfloat16* qb = qs + ((size_t)bh * SEQ + t) * 128 + d4 * 4;
        *(uint2*)(qb)      = hp;
        *(uint2*)(qb + 64) = lp;
    }
    {   // K
        __nv_bfloat16 h0,h1,h2,h3,l0,l1,l2,l3;
        split_bf16(kv.x, h0, l0); split_bf16(kv.y, h1, l1);
        split_bf16(kv.z, h2, l2); split_bf16(kv.w, h3, l3);
        uint2 hp, lp;
        *(__nv_bfloat162*)&hp.x = __halves2bfloat162(h0, h1);
        *(__nv_bfloat162*)&hp.y = __halves2bfloat162(h2, h3);
        *(__nv_bfloat162*)&lp.x = __halves2bfloat162(l0, l1);
        *(__nv_bfloat162*)&lp.y = __halves2bfloat162(l2, l3);
        __nv_bfloat16* kb = ks + ((size_t)bh * SEQ + t) * 128 + d4 * 4;
        *(uint2*)(kb)      = hp;
        *(uint2*)(kb + 64) = lp;
    }
    {   // V^T
        float vs[4] = {vv.x, vv.y, vv.z, vv.w};
#pragma unroll
        for (int j = 0; j < 4; j++) {
            __nv_bfloat16 hi, lo;
            split_bf16(vs[j], hi, lo);
            __nv_bfloat16* vb = vt + ((size_t)bh * DK + d4 * 4 + j) * (2 * SEQ);
            vb[t] = hi; vb[SEQ + t] = lo;
        }
    }
}

// ---------------------------------------------------------------------------
// mma.sync common pieces
// ---------------------------------------------------------------------------
#define STAGE_BYTES 32768
#define GEMM_DSMEM  (2 * STAGE_BYTES)
#define FA_STAGE    65536          // Khi 16K | Klo 16K | V 4x8K
#define FA_DSMEM    (32768 + 2 * FA_STAGE)   // Q 32K + 2 stages = 160K

__device__ __forceinline__ uint32_t smem_u32(const void* p) {
    uint32_t a;
    asm("{ .reg .u64 t; cvta.to.shared.u64 t, %1; cvt.u32.u64 %0, t; }" : "=r"(a) : "l"(p));
    return a;
}

#define CP_ASYNC16(dst, src) \
    asm volatile("cp.async.cg.shared.global [%0], [%1], 16;" :: "r"(dst), "l"(src) : "memory")
#define CP_COMMIT() asm volatile("cp.async.commit_group;" ::: "memory")
#define CP_WAIT1()  asm volatile("cp.async.wait_group 1;" ::: "memory")

#define LDMATRIX_X4(r0, r1, r2, r3, addr) \
    asm volatile("ldmatrix.sync.aligned.m8n8.x4.shared.b16 {%0,%1,%2,%3}, [%4];" \
        : "=r"(r0), "=r"(r1), "=r"(r2), "=r"(r3) : "r"(addr))

__device__ __forceinline__ void mma16816(float* d, const uint32_t* a, const uint32_t* b) {
    asm volatile(
        "mma.sync.aligned.m16n8k16.row.col.f32.bf16.bf16.f32 "
        "{%0,%1,%2,%3}, {%4,%5,%6,%7}, {%8,%9}, {%0,%1,%2,%3};"
        : "+f"(d[0]), "+f"(d[1]), "+f"(d[2]), "+f"(d[3])
        : "r"(a[0]), "r"(a[1]), "r"(a[2]), "r"(a[3]), "r"(b[0]), "r"(b[1]));
}

// ---------------------------------------------------------------------------
// Linear GEMM (unchanged, verified): C[M,N] = A[M,Kp] @ B[N,Kp]^T
// EP: 0 = fp32 out, 1 = fp32 + residual, 2 = relu + split-bf16 out (A-style)
// ---------------------------------------------------------------------------
template<int EP>
__global__ __launch_bounds__(256) void mma_gemm(
    const __nv_bfloat16* __restrict__ A, const __nv_bfloat16* __restrict__ B,
    const float* __restrict__ bias, const float* __restrict__ res,
    float* __restrict__ Cf, __nv_bfloat16* __restrict__ Cb,
    int N, int Kp)
{
    extern __shared__ __align__(16) char dsm[];
    const uint32_t sbase = smem_u32(dsm);

    const int tid  = threadIdx.x;
    const int wid  = tid >> 5;
    const int lane = tid & 31;
    const int g    = lane >> 2;
    const int cq   = lane & 3;
    const int lr   = lane & 15;
    const int lc   = lane >> 4;
    const int wm   = wid & 3;
    const int wn   = wid >> 2;
    const int n0   = blockIdx.x * 128;
    const int m0   = blockIdx.y * 128;

    const __nv_bfloat16* Ap = A + (size_t)m0 * Kp;
    const __nv_bfloat16* Bp = B + (size_t)n0 * Kp;
    const int nchunk = Kp >> 6;

    float acc[2][8][4];
#pragma unroll
    for (int mi = 0; mi < 2; mi++)
#pragma unroll
        for (int ni = 0; ni < 8; ni++)
#pragma unroll
            for (int r = 0; r < 4; r++) acc[mi][ni][r] = 0.0f;

    auto load_stage = [&](int c, int stage) {
        const int k0 = c << 6;
        const uint32_t sA = sbase + stage * STAGE_BYTES;
        const uint32_t sB = sA + 16384;
#pragma unroll
        for (int i = 0; i < 4; i++) {
            int lin = tid + i * 256;
            int r   = lin >> 3;
            int c16 = lin & 7;
            uint32_t off = (uint32_t)(r * 128 + ((c16 ^ (r & 7)) * 16));
            CP_ASYNC16(sA + off, (const void*)(Ap + (size_t)r * Kp + k0 + c16 * 8));
            CP_ASYNC16(sB + off, (const void*)(Bp + (size_t)r * Kp + k0 + c16 * 8));
        }
    };

    load_stage(0, 0);
    CP_COMMIT();

    for (int c = 0; c < nchunk; c++) {
        const int cur = c & 1;
        if (c + 1 < nchunk) load_stage(c + 1, cur ^ 1);
        CP_COMMIT();
        CP_WAIT1();
        __syncthreads();

        const uint32_t sA = sbase + cur * STAGE_BYTES;
        const uint32_t sB = sA + 16384;

#pragma unroll
        for (int ks = 0; ks < 4; ks++) {
            const int kblk = ks * 2 + lc;
            uint32_t afr[2][4], bfr[4][4];
#pragma unroll
            for (int mi = 0; mi < 2; mi++) {
                int row = wm * 32 + mi * 16 + lr;
                uint32_t addr = sA + (uint32_t)(row * 128 + ((kblk ^ (row & 7)) * 16));
                LDMATRIX_X4(afr[mi][0], afr[mi][1], afr[mi][2], afr[mi][3], addr);
            }
#pragma unroll
            for (int p = 0; p < 4; p++) {
                int row = wn * 64 + p * 16 + lr;
                uint32_t addr = sB + (uint32_t)(row * 128 + ((kblk ^ (row & 7)) * 16));
                LDMATRIX_X4(bfr[p][0], bfr[p][1], bfr[p][2], bfr[p][3], addr);
            }
#pragma unroll
            for (int mi = 0; mi < 2; mi++)
#pragma unroll
                for (int ni = 0; ni < 8; ni++) {
                    const int p = ni >> 1, o = ni & 1;
                    uint32_t b2[2] = { bfr[p][o], bfr[p][2 + o] };
                    mma16816(acc[mi][ni], afr[mi], b2);
                }
        }
        __syncthreads();
    }

#pragma unroll
    for (int mi = 0; mi < 2; mi++) {
#pragma unroll
        for (int half = 0; half < 2; half++) {
            const int m = m0 + wm * 32 + mi * 16 + g + half * 8;
#pragma unroll
            for (int ni = 0; ni < 8; ni++) {
                const int n = n0 + wn * 64 + ni * 8 + 2 * cq;
                float2 bv = *(const float2*)(bias + n);
                float v0 = acc[mi][ni][half * 2 + 0] + bv.x;
                float v1 = acc[mi][ni][half * 2 + 1] + bv.y;
                if (EP == 2) {
                    v0 = fmaxf(v0, 0.f); v1 = fmaxf(v1, 0.f);
                    __nv_bfloat16 h0, h1, l0, l1;
                    split_bf16(v0, h0, l0); split_bf16(v1, h1, l1);
                    uint32_t hp, lp;
                    *(__nv_bfloat162*)&hp = __halves2bfloat162(h0, h1);
                    *(__nv_bfloat162*)&lp = __halves2bfloat162(l0, l1);
                    size_t rb = (size_t)m * 3 * N;
                    *(uint32_t*)(Cb + rb + n)         = hp;
                    *(uint32_t*)(Cb + rb + N + n)     = hp;
                    *(uint32_t*)(Cb + rb + 2 * N + n) = lp;
                } else {
                    if (EP == 1) {
                        float2 rv = *(const float2*)(res + (size_t)m * N + n);
                        v0 += rv.x; v1 += rv.y;
                    }
                    *(float2*)(Cf + (size_t)m * N + n) = make_float2(v0, v1);
                }
            }
        }
    }
}

// ---------------------------------------------------------------------------
// Fused flash attention (no-max softmax): per CTA = 128 q rows of one (b,h).
// 8 warps x 16-row stripes, full 128-col S per warp. 2-stage cp.async K/V.
// S = Qs·Ks^T (3-term split via hi/lo slabs); P = exp(S) kept in registers as
// A-fragments (C-frag == A-frag layout); ctx = P·V^T (3-term) / rowsum.
// Writes ctx directly in the split [hi|hi|lo] layout for the Wo GEMM.
// ---------------------------------------------------------------------------
__global__ __launch_bounds__(256) void flash_attn(
    const __nv_bfloat16* __restrict__ qs, const __nv_bfloat16* __restrict__ ks,
    const __nv_bfloat16* __restrict__ vt, __nv_bfloat16* __restrict__ Ccvt)
{
    extern __shared__ __align__(16) char dsm[];
    const uint32_t sb  = smem_u32(dsm);
    const uint32_t Qhi = sb;               // [128][64] bf16
    const uint32_t Qlo = sb + 16384;
    const uint32_t ST0 = sb + 32768;       // stage: Khi 16K | Klo 16K | V 4x8K

    const int tid  = threadIdx.x;
    const int wid  = tid >> 5;
    const int lane = tid & 31;
    const int g    = lane >> 2;
    const int cq   = lane & 3;
    const int lr   = lane & 15;
    const int lc   = lane >> 4;
    const int q0   = blockIdx.x * 128;
    const int bh   = blockIdx.y;
    const int b    = bh >> 3, h = bh & 7;

    // --- load Q (once) ---
#pragma unroll
    for (int i = 0; i < 8; i++) {
        int id = tid + i * 256;
        int slab = id >> 10, r = (id >> 3) & 127, u = id & 7;
        const __nv_bfloat16* src = qs + ((size_t)bh * SEQ + q0 + r) * 128 + slab * 64 + u * 8;
        CP_ASYNC16((slab ? Qlo : Qhi) + (uint32_t)(r * 128 + ((u ^ (r & 7)) * 16)), src);
    }

    auto load_kv = [&](int st, uint32_t stage) {
        const int s0 = st * 128;
#pragma unroll
        for (int i = 0; i < 8; i++) {          // K: 2 slabs x 128 rows x 8 units
            int id = tid + i * 256;
            int slab = id >> 10, r = (id >> 3) & 127, u = id & 7;
            const __nv_bfloat16* src = ks + ((size_t)bh * SEQ + s0 + r) * 128 + slab * 64 + u * 8;
            CP_ASYNC16(stage + slab * 16384 + (uint32_t)(r * 128 + ((u ^ (r & 7)) * 16)), src);
        }
#pragma unroll
        for (int i = 0; i < 8; i++) {          // V: 4 slabs x 64 rows x 8 units
            int id = tid + i * 256;
            int slab = id >> 9;                // 0:hi_a 1:hi_b 2:lo_a 3:lo_b
            int r = (id >> 3) & 63, u = id & 7;
            int col = (slab >> 1) * SEQ + s0 + (slab & 1) * 64 + u * 8;
            const __nv_bfloat16* src = vt + ((size_t)bh * DK + r) * (2 * SEQ) + col;
            CP_ASYNC16(stage + 32768 + slab * 8192 + (uint32_t)(r * 128 + ((u ^ (r & 7)) * 16)), src);
        }
    };

    load_kv(0, ST0);
    CP_COMMIT();

    float oacc[8][4];
#pragma unroll
    for (int ni = 0; ni < 8; ni++)
#pragma unroll
        for (int r = 0; r < 4; r++) oacc[ni][r] = 0.0f;
    float lsum0 = 0.0f, lsum1 = 0.0f;

    const int arow = wid * 16 + lr;
    const uint32_t aoff = (uint32_t)(arow * 128);

    for (int st = 0; st < 8; st++) {
        const int cur = st & 1;
        if (st + 1 < 8) load_kv(st + 1, ST0 + (cur ^ 1) * FA_STAGE);
        CP_COMMIT();
        CP_WAIT1();
        __syncthreads();

        const uint32_t Kh = ST0 + cur * FA_STAGE;
        const uint32_t Kl = Kh + 16384;
        const uint32_t Vb = Kh + 32768;

        // ---- S = Q K^T (3 logical slabs) ----
        float sacc[16][4];
#pragma unroll
        for (int ni = 0; ni < 16; ni++)
#pragma unroll
            for (int r = 0; r < 4; r++) sacc[ni][r] = 0.0f;

        uint32_t ahi[4][4];
#pragma unroll
        for (int j = 0; j < 4; j++) {
            const int kblk = j * 2 + lc;
            const uint32_t asw = (uint32_t)((kblk ^ (arow & 7)) * 16);
            LDMATRIX_X4(ahi[j][0], ahi[j][1], ahi[j][2], ahi[j][3], Qhi + aoff + asw);
#pragma unroll
            for (int p = 0; p < 8; p++) {
                int row = p * 16 + lr;
                uint32_t addr = Kh + (uint32_t)(row * 128 + ((kblk ^ (row & 7)) * 16));
                uint32_t bfr[4];
                LDMATRIX_X4(bfr[0], bfr[1], bfr[2], bfr[3], addr);
#pragma unroll
                for (int o = 0; o < 2; o++) {
                    uint32_t b2[2] = { bfr[o], bfr[2 + o] };
                    mma16816(sacc[2 * p + o], ahi[j], b2);
                }
            }
#pragma unroll
            for (int p = 0; p < 8; p++) {
                int row = p * 16 + lr;
                uint32_t addr = Kl + (uint32_t)(row * 128 + ((kblk ^ (row & 7)) * 16));
                uint32_t bfr[4];
                LDMATRIX_X4(bfr[0], bfr[1], bfr[2], bfr[3], addr);
#pragma unroll
                for (int o = 0; o < 2; o++) {
                    uint32_t b2[2] = { bfr[o], bfr[2 + o] };
                    mma16816(sacc[2 * p + o], ahi[j], b2);
                }
            }
        }
#pragma unroll
        for (int j = 0; j < 4; j++) {
            const int kblk = j * 2 + lc;
            const uint32_t asw = (uint32_t)((kblk ^ (arow & 7)) * 16);
            uint32_t alo[4];
            LDMATRIX_X4(alo[0], alo[1], alo[2], alo[3], Qlo + aoff + asw);
#pragma unroll
            for (int p = 0; p < 8; p++) {
                int row = p * 16 + lr;
                uint32_t addr = Kh + (uint32_t)(row * 128 + ((kblk ^ (row & 7)) * 16));
                uint32_t bfr[4];
                LDMATRIX_X4(bfr[0], bfr[1], bfr[2], bfr[3], addr);
#pragma unroll
                for (int o = 0; o < 2; o++) {
                    uint32_t b2[2] = { bfr[o], bfr[2 + o] };
                    mma16816(sacc[2 * p + o], alo, b2);
                }
            }
        }

        // ---- P = exp(S); accumulate row sums; build hi A-fragments ----
#pragma unroll
        for (int ni = 0; ni < 16; ni++) {
            float p0 = __expf(sacc[ni][0]);
            float p1 = __expf(sacc[ni][1]);
            float p2 = __expf(sacc[ni][2]);
            float p3 = __expf(sacc[ni][3]);
            lsum0 += p0 + p1;
            lsum1 += p2 + p3;
            sacc[ni][0] = p0; sacc[ni][1] = p1;
            sacc[ni][2] = p2; sacc[ni][3] = p3;
        }
        uint32_t phi[8][4];
#pragma unroll
        for (int jj = 0; jj < 8; jj++) {
            phi[jj][0] = packbf(sacc[2 * jj][0],     sacc[2 * jj][1]);
            phi[jj][1] = packbf(sacc[2 * jj][2],     sacc[2 * jj][3]);
            phi[jj][2] = packbf(sacc[2 * jj + 1][0], sacc[2 * jj + 1][1]);
            phi[jj][3] = packbf(sacc[2 * jj + 1][2], sacc[2 * jj + 1][3]);
        }

        // ---- ctx += P V^T (3 logical slabs) ----
#pragma unroll
        for (int jj = 0; jj < 8; jj++) {
            const int kblk = (jj & 3) * 2 + lc;
            const uint32_t baseH = Vb + (jj >> 2) * 8192;
            const uint32_t baseL = Vb + 16384 + (jj >> 2) * 8192;
            // P_hi x V_hi
#pragma unroll
            for (int p = 0; p < 4; p++) {
                int row = p * 16 + lr;
                uint32_t addr = baseH + (uint32_t)(row * 128 + ((kblk ^ (row & 7)) * 16));
                uint32_t bfr[4];
                LDMATRIX_X4(bfr[0], bfr[1], bfr[2], bfr[3], addr);
#pragma unroll
                for (int o = 0; o < 2; o++) {
                    uint32_t b2[2] = { bfr[o], bfr[2 + o] };
                    mma16816(oacc[2 * p + o], phi[jj], b2);
                }
            }
            // P_hi x V_lo
#pragma unroll
            for (int p = 0; p < 4; p++) {
                int row = p * 16 + lr;
                uint32_t addr = baseL + (uint32_t)(row * 128 + ((kblk ^ (row & 7)) * 16));
                uint32_t bfr[4];
                LDMATRIX_X4(bfr[0], bfr[1], bfr[2], bfr[3], addr);
#pragma unroll
                for (int o = 0; o < 2; o++) {
                    uint32_t b2[2] = { bfr[o], bfr[2 + o] };
                    mma16816(oacc[2 * p + o], phi[jj], b2);
                }
            }
            // P_lo x V_hi
            uint32_t plo[4];
            plo[0] = packbf(lof(sacc[2 * jj][0]),     lof(sacc[2 * jj][1]));
            plo[1] = packbf(lof(sacc[2 * jj][2]),     lof(sacc[2 * jj][3]));
            plo[2] = packbf(lof(sacc[2 * jj + 1][0]), lof(sacc[2 * jj + 1][1]));
            plo[3] = packbf(lof(sacc[2 * jj + 1][2]), lof(sacc[2 * jj + 1][3]));
#pragma unroll
            for (int p = 0; p < 4; p++) {
                int row = p * 16 + lr;
                uint32_t addr = baseH + (uint32_t)(row * 128 + ((kblk ^ (row & 7)) * 16));
                uint32_t bfr[4];
                LDMATRIX_X4(bfr[0], bfr[1], bfr[2], bfr[3], addr);
#pragma unroll
                for (int o = 0; o < 2; o++) {
                    uint32_t b2[2] = { bfr[o], bfr[2 + o] };
                    mma16816(oacc[2 * p + o], plo, b2);
                }
            }
        }
        __syncthreads();
    }

    // row-sum reduction over the quad (cq lanes)
    lsum0 += __shfl_xor_sync(0xffffffffu, lsum0, 1);
    lsum0 += __shfl_xor_sync(0xffffffffu, lsum0, 2);
    lsum1 += __shfl_xor_sync(0xffffffffu, lsum1, 1);
    lsum1 += __shfl_xor_sync(0xffffffffu, lsum1, 2);
    const float inv0 = 1.0f / lsum0;
    const float inv1 = 1.0f / lsum1;

    // epilogue: split write into g_ccvt [tok][3*512] at cols h*64 + n
#pragma unroll
    for (int half = 0; half < 2; half++) {
        const int m = q0 + wid * 16 + g + half * 8;
        const size_t tok = (size_t)b * SEQ + m;
        const size_t rb = tok * (3 * NU);
        const float inv = half ? inv1 : inv0;
#pragma unroll
        for (int ni = 0; ni < 8; ni++) {
            const int col = h * DK + ni * 8 + 2 * cq;
            float v0 = oacc[ni][half * 2 + 0] * inv;
            float v1 = oacc[ni][half * 2 + 1] * inv;
            __nv_bfloat16 h0, h1, l0, l1;
            split_bf16(v0, h0, l0); split_bf16(v1, h1, l1);
            uint32_t hp, lp;
            *(__nv_bfloat162*)&hp = __halves2bfloat162(h0, h1);
            *(__nv_bfloat162*)&lp = __halves2bfloat162(l0, l1);
            *(uint32_t*)(Ccvt + rb + col)          = hp;
            *(uint32_t*)(Ccvt + rb + NU + col)     = hp;
            *(uint32_t*)(Ccvt + rb + 2 * NU + col) = lp;
        }
    }
}

// ---------------------------------------------------------------------------
// LayerNorm over rows of 512; optionally also writes split-bf16 (A-style)
// ---------------------------------------------------------------------------
template<bool CVT>
__global__ __launch_bounds__(128) void ln_kernel(
    const float* __restrict__ X, const float* __restrict__ gamma,
    const float* __restrict__ beta, float* __restrict__ O,
    __nv_bfloat16* __restrict__ Ocvt)
{
    __shared__ float red[4];
    const int row = blockIdx.x;
    const int tid = threadIdx.x;

    float4 v = *(const float4*)(X + (size_t)row * NU + tid * 4);
    float s = v.x + v.y + v.z + v.w;
#pragma unroll
    for (int o = 16; o > 0; o >>= 1) s += __shfl_xor_sync(0xffffffffu, s, o);
    if ((tid & 31) == 0) red[tid >> 5] = s;
    __syncthreads();
    float mean = (red[0] + red[1] + red[2] + red[3]) * (1.0f / 512.0f);
    __syncthreads();

    float dx = v.x - mean, dy = v.y - mean, dz = v.z - mean, dw = v.w - mean;
    float sq = dx * dx + dy * dy + dz * dz + dw * dw;
#pragma unroll
    for (int o = 16; o > 0; o >>= 1) sq += __shfl_xor_sync(0xffffffffu, sq, o);
    if ((tid & 31) == 0) red[tid >> 5] = sq;
    __syncthreads();
    float var = (red[0] + red[1] + red[2] + red[3]) * (1.0f / 512.0f);
    float inv = rsqrtf(var + 1e-5f);

    float4 g = *(const float4*)(gamma + tid * 4);
    float4 b = *(const float4*)(beta  + tid * 4);
    float4 o4;
    o4.x = dx * inv * g.x + b.x;
    o4.y = dy * inv * g.y + b.y;
    o4.z = dz * inv * g.z + b.z;
    o4.w = dw * inv * g.w + b.w;
    *(float4*)(O + (size_t)row * NU + tid * 4) = o4;

    if (CVT) {
        __nv_bfloat16 h0, h1, h2, h3, l0, l1, l2, l3;
        split_bf16(o4.x, h0, l0); split_bf16(o4.y, h1, l1);
        split_bf16(o4.z, h2, l2); split_bf16(o4.w, h3, l3);
        uint2 hp, lp;
        *(__nv_bfloat162*)&hp.x = __halves2bfloat162(h0, h1);
        *(__nv_bfloat162*)&hp.y = __halves2bfloat162(h2, h3);
        *(__nv_bfloat162*)&lp.x = __halves2bfloat162(l0, l1);
        *(__nv_bfloat162*)&lp.y = __halves2bfloat162(l2, l3);
        size_t rb = (size_t)row * (3 * NU);
        int col = tid * 4;
        *(uint2*)(Ocvt + rb + col)            = hp;
        *(uint2*)(Ocvt + rb + NU + col)       = hp;
        *(uint2*)(Ocvt + rb + 2 * NU + col)   = lp;
    }
}

// ---------------------------------------------------------------------------
// Host orchestration (graph-capturable: kernel launches only)
// ---------------------------------------------------------------------------
extern "C" void kernel_launch(void* const* d_in, const int* in_sizes, int n_in,
                              void* d_out, int out_size)
{
    (void)in_sizes; (void)n_in; (void)out_size;

    const float* x     = (const float*)d_in[0];
    const float* Win   = (const float*)d_in[1];
    const float* bin   = (const float*)d_in[2];
    const float* ln1_g = (const float*)d_in[3];
    const float* ln1_b = (const float*)d_in[4];
    const float* Wq    = (const float*)d_in[5];
    const float* bq    = (const float*)d_in[6];
    const float* Wk    = (const float*)d_in[7];
    const float* bk    = (const float*)d_in[8];
    const float* Wv    = (const float*)d_in[9];
    const float* bv    = (const float*)d_in[10];
    const float* Wo    = (const float*)d_in[11];
    const float* bo    = (const float*)d_in[12];
    const float* ln2_g = (const float*)d_in[13];
    const float* ln2_b = (const float*)d_in[14];
    const float* W1    = (const float*)d_in[15];
    const float* b1    = (const float*)d_in[16];
    const float* W2    = (const float*)d_in[17];
    const float* b2    = (const float*)d_in[18];
    const float* lno_g = (const float*)d_in[19];
    const float* lno_b = (const float*)d_in[20];
    float* out = (float*)d_out;

    float *e, *qkv, *bqkv;
    __nv_bfloat16 *xc, *ec, *cc, *hc, *Winc, *Wqkvc, *Woc, *W1c, *W2c;
    __nv_bfloat16 *qs, *ks, *vt;
    cudaGetSymbolAddress((void**)&e,    g_e);
    cudaGetSymbolAddress((void**)&qkv,  g_qkv);
    cudaGetSymbolAddress((void**)&bqkv, g_bqkv);
    cudaGetSymbolAddress((void**)&xc,   g_xcvt);
    cudaGetSymbolAddress((void**)&ec,   g_ecvt);
    cudaGetSymbolAddress((void**)&cc,   g_ccvt);
    cudaGetSymbolAddress((void**)&hc,   g_hcvt);
    cudaGetSymbolAddress((void**)&Winc,  g_Winc);
    cudaGetSymbolAddress((void**)&Wqkvc, g_Wqkvc);
    cudaGetSymbolAddress((void**)&Woc,   g_Woc);
    cudaGetSymbolAddress((void**)&W1c,   g_W1c);
    cudaGetSymbolAddress((void**)&W2c,   g_W2c);
    cudaGetSymbolAddress((void**)&qs,   g_qs);
    cudaGetSymbolAddress((void**)&ks,   g_ks);
    cudaGetSymbolAddress((void**)&vt,   g_vt);

    cudaFuncSetAttribute(mma_gemm<0>, cudaFuncAttributeMaxDynamicSharedMemorySize, GEMM_DSMEM);
    cudaFuncSetAttribute(mma_gemm<1>, cudaFuncAttributeMaxDynamicSharedMemorySize, GEMM_DSMEM);
    cudaFuncSetAttribute(mma_gemm<2>, cudaFuncAttributeMaxDynamicSharedMemorySize, GEMM_DSMEM);
    cudaFuncSetAttribute(flash_attn,  cudaFuncAttributeMaxDynamicSharedMemorySize, FA_DSMEM);

    // operand conversions (every launch; deterministic)
    {
        int t;
        t = NU * IDIM;          convert_B_kernel<<<(t + 255) / 256, 256>>>(Win, Winc, IDIM, t);
        for (int i = 0; i < NLAYERS; i++) {
            const size_t lb = (size_t)i * QKVW * 3 * NU;
            int tt = NU * NU;
            convert_B_kernel<<<(tt + 255) / 256, 256>>>(Wq + (size_t)i * NU * NU, Wqkvc + lb, NU, tt);
            convert_B_kernel<<<(tt + 255) / 256, 256>>>(Wk + (size_t)i * NU * NU, Wqkvc + lb + (size_t)NU * 3 * NU, NU, tt);
            convert_B_kernel<<<(tt + 255) / 256, 256>>>(Wv + (size_t)i * NU * NU, Wqkvc + lb + (size_t)2 * NU * 3 * NU, NU, tt);
        }
        t = NLAYERS * NU * NU;  convert_B_kernel<<<(t + 255) / 256, 256>>>(Wo, Woc, NU, t);
        t = NLAYERS * EU * NU;  convert_B_kernel<<<(t + 255) / 256, 256>>>(W1, W1c, NU, t);
        t = NLAYERS * NU * EU;  convert_B_kernel<<<(t + 255) / 256, 256>>>(W2, W2c, EU, t);
        t = TOK * IDIM;         convert_A_kernel<<<(t + 255) / 256, 256>>>(x, xc, IDIM, t);
        t = NLAYERS * QKVW;     pack_bqkv_kernel<<<(t + 255) / 256, 256>>>(bq, bk, bv, bqkv);
    }

    dim3 g512 (NU   / 128, TOK / 128);   // (4, 64)
    dim3 gqkv (QKVW / 128, TOK / 128);   // (12, 64)
    dim3 g2048(EU   / 128, TOK / 128);   // (16, 64)
    dim3 gflash(SEQ / 128, BH);          // (8, 64)
    const int cvattn_blocks = (BH * SEQ * 16 + 255) / 256;

    // input projection: e = x @ Win^T + bin
    mma_gemm<0><<<g512, 256, GEMM_DSMEM>>>(xc, Winc, bin, nullptr, e, nullptr, NU, 3 * IDIM);

    for (int i = 0; i < NLAYERS; i++) {
        const size_t wqkv = (size_t)i * QKVW * 3 * NU;
        const size_t wo   = (size_t)i * NU * 3 * NU;
        const size_t w1o  = (size_t)i * EU * 3 * NU;
        const size_t w2o  = (size_t)i * NU * 3 * EU;

        ln_kernel<true><<<TOK, 128>>>(e, ln1_g + i * NU, ln1_b + i * NU, e, ec);

        // fused qkv = ln(e) @ [Wq|Wk|Wv]^T + [bq|bk|bv]
        mma_gemm<0><<<gqkv, 256, GEMM_DSMEM>>>(ec, Wqkvc + wqkv, bqkv + i * QKVW, nullptr,
                                               qkv, nullptr, QKVW, 3 * NU);

        // fused attention
        convert_attn_kernel<<<cvattn_blocks, 256>>>(qkv, qs, ks, vt);
        flash_attn<<<gflash, 256, FA_DSMEM>>>(qs, ks, vt, cc);

        // e = e + ctx @ Wo^T + bo
        mma_gemm<1><<<g512, 256, GEMM_DSMEM>>>(cc, Woc + wo, bo + i * NU, e, e, nullptr, NU, 3 * NU);

        ln_kernel<true><<<TOK, 128>>>(e, ln2_g + i * NU, ln2_b + i * NU, e, ec);

        // h = relu(e @ W1^T + b1) -> split bf16
        mma_gemm<2><<<g2048, 256, GEMM_DSMEM>>>(ec, W1c + w1o, b1 + (size_t)i * EU, nullptr,
                                                nullptr, hc, EU, 3 * NU);
        // e = e + h @ W2^T + b2
        mma_gemm<1><<<g512, 256, GEMM_DSMEM>>>(hc, W2c + w2o, b2 + i * NU, e, e, nullptr, NU, 3 * EU);
    }

    ln_kernel<false><<<TOK, 128>>>(e, lno_g, lno_b, out, nullptr);
}